// round 11
// baseline (speedup 1.0000x reference)
#include <cuda_runtime.h>
#include <math.h>

#define Bq 8
#define Cc 64
#define Ll 784
#define HIDd 128
#define Sdim 64
#define NHh 16
#define DIMc 256
#define PT 49
#define NTt 16

// ---------------- scratch ----------------
__device__ float g_x1o [Bq*Cc*Ll];
__device__ float g_x1g [Bq*Cc*Ll];
__device__ float g_b1  [Bq*Cc*Ll];
__device__ float g_b2  [Bq*Cc*Ll];
__device__ float g_bcdt1[Bq*192*Ll];
__device__ float g_wsl [Bq*Sdim*Ll];
__device__ float g_b3  [Bq*Cc*Ll];
__device__ float g_qb  [Bq*NHh*Ll*4];
__device__ float g_kb  [Bq*NHh*Ll*4];
__device__ float g_vb  [Bq*NHh*Ll*4];
__device__ float g_ob  [Bq*Ll*Cc];
__device__ float g_b4  [Bq*Cc*Ll];

__device__ __forceinline__ float bnf(float x, const float* __restrict__ p, int c, int C){
    return (x - p[2*C+c]) * p[c] * rsqrtf(p[3*C+c] + 1e-5f) + p[C+c];
}

__device__ __forceinline__ unsigned long long pk2(float a, float b){
    unsigned long long r; asm("mov.b64 %0, {%1,%2};" : "=l"(r) : "f"(a), "f"(b)); return r;
}
__device__ __forceinline__ void upk2(unsigned long long v, float& a, float& b){
    asm("mov.b64 {%0,%1}, %2;" : "=f"(a), "=f"(b) : "l"(v));
}
__device__ __forceinline__ unsigned long long fma2(unsigned long long a, unsigned long long b, unsigned long long c){
    unsigned long long r; asm("fma.rn.f32x2 %0, %1, %2, %3;" : "=l"(r) : "l"(a), "l"(b), "l"(c)); return r;
}
__device__ __forceinline__ unsigned long long mul2(unsigned long long a, unsigned long long b){
    unsigned long long r; asm("mul.rn.f32x2 %0, %1, %2;" : "=l"(r) : "l"(a), "l"(b)); return r;
}

// =======================================================================
// STAGE A (256 thr): dw7a | att2(full branch2) | bcdt | qkv
// grid: [0,1568) dw7a, [1568,2080) att2, [2080,2208) bcdt, [2208,2336) qkv
// =======================================================================
__global__ void __launch_bounds__(256,1)
k_stageA(const float* __restrict__ x,
         const float* __restrict__ dw1_w, const float* __restrict__ dw1_b,
         const float* __restrict__ bn_dw1,
         const float* __restrict__ wh1, const float* __restrict__ wv1,
         const float* __restrict__ wh2, const float* __restrict__ wv2,
         const float* __restrict__ bnm,
         const float* __restrict__ bcdt_w, const float* __restrict__ qkv_w){
    extern __shared__ float pool[];
    int tid = threadIdx.x;
    int bid = blockIdx.x;

    if (bid < 1568){
        // ---- dw7a: depthwise 7x7 + bias + BN on quarter 0 ----
        int idx = bid*256 + tid;
        int p = idx % Ll; int c = (idx/Ll) % Cc; int b = idx/(Ll*Cc);
        int y = p/28, xx = p%28;
        const float* ip = x + ((size_t)(b*DIMc + c))*Ll;
        const float* wc = dw1_w + c*49;
        float acc = dw1_b[c];
        #pragma unroll
        for (int ky=0; ky<7; ky++){
            int yy = y+ky-3; if ((unsigned)yy >= 28u) continue;
            #pragma unroll
            for (int kx=0; kx<7; kx++){
                int xw = xx+kx-3; if ((unsigned)xw >= 28u) continue;
                acc += wc[ky*7+kx] * ip[yy*28+xw];
            }
        }
        g_x1o[idx] = bnf(acc, bn_dw1, c, Cc);
        return;
    }
    if (bid < 2080){
        // ---- att2: full branch 2 for one (b,c) ----
        float* mp   = pool;          // 784
        float* xt   = pool + 784;    // 100
        float* sacc = pool + 884;    // 100
        float* sh   = pool + 984;    // 190
        float* cbuf = pool + 1174;   // 190
        float* sw1  = pool + 1364;   // 33
        float* sw2  = pool + 1397;
        float* sw3  = pool + 1430;
        float* sw4  = pool + 1463;
        int bc = bid - 1568; int b = bc/64, c = bc%64;
        if (tid < 33){ sw1[tid]=wh1[c*33+tid]; sw2[tid]=wv1[c*33+tid];
                       sw3[tid]=wh2[c*33+tid]; sw4[tid]=wv2[c*33+tid]; }
        const float* x2 = x + ((size_t)(b*DIMc + 64 + c))*Ll;
        for (int p=tid; p<784; p+=256){
            int y=p/28, xx=p%28;
            float m = -1e30f;
            #pragma unroll
            for (int dy=-1; dy<=1; dy++){ int yy=y+dy; if ((unsigned)yy>=28u) continue;
                #pragma unroll
                for (int dx=-1; dx<=1; dx++){ int xw=xx+dx; if ((unsigned)xw>=28u) continue;
                    m = fmaxf(m, x2[yy*28+xw]); } }
            mp[p] = m;
        }
        __syncthreads();
        if (tid < 100){
            int oy = tid/10, ox = tid%10;
            const float fa[4] = {1.f,3.f,3.f,1.f};
            float acc = 0.f;
            #pragma unroll
            for (int ty=0; ty<4; ty++){
                int q = 3*oy + ty - 1; if (q < 0) q = -q; if (q >= 28) q = 54 - q;
                #pragma unroll
                for (int tx=0; tx<4; tx++){
                    int r = 3*ox + tx - 1; if (r < 0) r = -r; if (r >= 28) r = 54 - r;
                    acc += fa[ty]*fa[tx]*mp[q*28+r];
                }
            }
            xt[tid] = acc * (1.0f/64.0f);
        }
        __syncthreads();
        if (tid < 100){
            int y = tid/10, xo = tid%10;
            float s = 0.f;
            #pragma unroll
            for (int ky=0; ky<11; ky++){ int yy=y+ky-5; if ((unsigned)yy>=10u) continue;
                #pragma unroll
                for (int kx=0; kx<3; kx++){ int xx=xo+kx-1; if ((unsigned)xx>=10u) continue;
                    s += sw1[ky*3+kx]*xt[yy*10+xx]; } }
            #pragma unroll
            for (int ky=0; ky<3; ky++){ int yy=y+ky-1; if ((unsigned)yy>=10u) continue;
                #pragma unroll
                for (int kx=0; kx<11; kx++){ int xx=xo+kx-5; if ((unsigned)xx>=10u) continue;
                    s += sw2[ky*11+kx]*xt[yy*10+xx]; } }
            sacc[tid] = s;
        }
        if (tid < 190){
            int r = tid/19, j = tid%19, d = j - r;
            sh[tid] = (d >= 0 && d < 10) ? xt[r*10 + d] : 0.f;
        }
        __syncthreads();
        if (tid < 190){
            int u = tid/19, v = tid%19;
            float s = 0.f;
            #pragma unroll
            for (int ky=0; ky<11; ky++){ int uu=u+ky-5; if ((unsigned)uu>=10u) continue;
                #pragma unroll
                for (int kx=0; kx<3; kx++){ int vv=v+kx-1; if ((unsigned)vv>=19u) continue;
                    s += sw3[ky*3+kx]*sh[uu*19+vv]; } }
            cbuf[tid] = s;
        }
        __syncthreads();
        if (tid < 100){
            int y = tid/10, xo = tid%10;
            sacc[tid] += cbuf[20*y + xo];
        }
        __syncthreads();
        if (tid < 190){
            int a = tid/10, b2 = tid%10, d = a - b2;
            sh[tid] = (d >= 0 && d < 10) ? xt[d*10 + b2] : 0.f;
        }
        __syncthreads();
        if (tid < 190){
            int a = tid/10, b2 = tid%10;
            float s = 0.f;
            #pragma unroll
            for (int ky=0; ky<3; ky++){ int av=a+ky-1; if ((unsigned)av>=19u) continue;
                #pragma unroll
                for (int kx=0; kx<11; kx++){ int bv=b2+kx-5; if ((unsigned)bv>=10u) continue;
                    s += sw4[ky*11+kx]*sh[av*10+bv]; } }
            cbuf[tid] = s;
        }
        __syncthreads();
        if (tid < 100){
            int y = tid/10, xo = tid%10;
            int g = 20*xo + y;
            float s = sacc[tid] + cbuf[(g%19)*10 + (g/19)];
            s = bnf(s, bnm, c, 64);
            sacc[tid] = 1.f/(1.f + __expf(-s));
        }
        __syncthreads();
        float* op = g_b2 + (size_t)bc*Ll;
        for (int p=tid; p<Ll; p+=256){
            int y = p/28, xx = p%28;
            op[p] = x2[p] * sacc[(y*10/28)*10 + (xx*10/28)];
        }
        return;
    }
    // ---- bcdt (192x64 pw on quarter 2) or qkv (192x64 pw on quarter 3) ----
    {
        int isQ = (bid >= 2208);
        int bidL = bid - (isQ ? 2208 : 2080);
        const float* w = isQ ? qkv_w : bcdt_w;
        int chOff = isQ ? 192 : 128;
        float* sw = pool;            // 192*65
        float* sx = pool + 192*65;   // 64*49
        int b = bidL / NTt, p0 = (bidL % NTt) * PT;
        for (int i=tid; i<192*64; i+=256){ sw[(i/64)*65 + (i%64)] = w[i]; }
        for (int i=tid; i<64*PT; i+=256){
            int c=i/PT, px=i%PT;
            sx[i] = x[((size_t)(b*DIMc + chOff + c))*Ll + p0+px];
        }
        __syncthreads();
        int og = tid % 48, pg = tid / 48;
        int o0 = og*4, px0 = pg*10;
        int cnt = PT - px0; if (cnt > 10) cnt = 10; if (cnt < 0) cnt = 0;
        float acc[4][10];
        #pragma unroll
        for (int k=0;k<4;k++)
            #pragma unroll
            for (int j=0;j<10;j++) acc[k][j]=0.f;
        if (cnt > 0){
            for (int c=0;c<64;c++){
                float w0=sw[(o0+0)*65+c], w1=sw[(o0+1)*65+c], w2=sw[(o0+2)*65+c], w3=sw[(o0+3)*65+c];
                #pragma unroll 10
                for (int j=0;j<10;j++){
                    if (j<cnt){
                        float xx = sx[c*PT + px0 + j];
                        acc[0][j]+=w0*xx; acc[1][j]+=w1*xx; acc[2][j]+=w2*xx; acc[3][j]+=w3*xx;
                    }
                }
            }
            if (!isQ){
                #pragma unroll
                for (int k=0;k<4;k++)
                    for (int j=0;j<cnt;j++)
                        g_bcdt1[((size_t)(b*192 + o0+k))*Ll + p0+px0+j] = acc[k][j];
            } else {
                #pragma unroll
                for (int k=0;k<4;k++){
                    int o = o0+k;
                    int part = o/64, rem = o%64, hh = rem/4, dd = rem%4;
                    float* dst = (part==0) ? g_qb : (part==1) ? g_kb : g_vb;
                    for (int j=0;j<cnt;j++)
                        dst[(((size_t)b*16 + hh)*Ll + p0+px0+j)*4 + dd] = acc[k][j];
                }
            }
        }
    }
}

// =======================================================================
// STAGE B (800 thr): star (chunked weights) | softAB (dw3 fused) | attn
// grid: [0,128) star, [128,640) softAB, [640,768) attn
// =======================================================================
__global__ void __launch_bounds__(800,1)
k_stageB(const float* __restrict__ f1w, const float* __restrict__ f1b,
         const float* __restrict__ f2w, const float* __restrict__ f2b,
         const float* __restrict__ gw,  const float* __restrict__ gb,
         const float* __restrict__ bng,
         const float* __restrict__ ssd_dw, const float* __restrict__ Ap){
    extern __shared__ float pool[];
    int tid = threadIdx.x;
    int bid = blockIdx.x;

    if (bid < 128){
        // ---- star MLP, weight chunks staged serially ----
        float* sxv = pool;           // 3136
        float* sa  = pool + 3136;    // 6272
        float* wb  = pool + 9408;    // 8192
        int b = bid/16, p0 = (bid%16)*PT;
        for (int i=tid; i<64*PT; i+=800){
            int c=i/PT, px=i%PT;
            sxv[i] = g_x1o[((size_t)(b*64+c))*Ll + p0+px];
        }
        for (int i=tid; i<8192; i+=800) wb[i] = f1w[i];
        __syncthreads();
        for (int i=tid; i<128*PT; i+=800){
            int h=i/PT, px=i%PT;
            float a = f1b[h];
            const float* wr = wb + h*64;
            #pragma unroll 8
            for (int c=0;c<64;c++) a += wr[c]*sxv[c*PT+px];
            sa[i] = a;
        }
        __syncthreads();
        for (int i=tid; i<8192; i+=800) wb[i] = f2w[i];
        __syncthreads();
        for (int i=tid; i<128*PT; i+=800){
            int h=i/PT, px=i%PT;
            float a2 = f2b[h];
            const float* wr = wb + h*64;
            #pragma unroll 8
            for (int c=0;c<64;c++) a2 += wr[c]*sxv[c*PT+px];
            float a1 = fminf(fmaxf(sa[i],0.f),6.f);
            sa[i] = a1*a2;
        }
        __syncthreads();
        for (int i=tid; i<8192; i+=800) wb[i] = gw[i];
        __syncthreads();
        for (int i=tid; i<64*PT; i+=800){
            int o=i/PT, px=i%PT;
            float acc = gb[o];
            const float* wr = wb + o*128;
            #pragma unroll 8
            for (int j=0;j<128;j++) acc += wr[j]*sa[j*PT+px];
            g_x1g[((size_t)(b*64+o))*Ll + p0+px] = bnf(acc, bng, o, 64);
        }
        return;
    }
    if (bid < 640){
        // ---- fused dw3 + softmax(dt+A)*Bm for one (b,s) ----
        float* rb  = pool;          // 784 (B source row)
        float* rd  = pool + 784;    // 784 (dt source row)
        float* red = pool + 1568;   // 32
        int bs = bid - 128; int b = bs/64, s = bs%64;
        for (int i=tid; i<784; i+=800){
            rb[i] = g_bcdt1[((size_t)(b*192 + s))*Ll + i];
            rd[i] = g_bcdt1[((size_t)(b*192 + 128 + s))*Ll + i];
        }
        __syncthreads();
        float dtv = -1e30f, bmv = 0.f;
        if (tid < 784){
            int y = tid/28, xx = tid%28;
            const float* wB = ssd_dw + s*9;
            const float* wD = ssd_dw + (128+s)*9;
            float ab = 0.f, ad = 0.f;
            #pragma unroll
            for (int ky=0; ky<3; ky++){
                int yy=y+ky-1; if ((unsigned)yy>=28u) continue;
                #pragma unroll
                for (int kx=0; kx<3; kx++){
                    int xw=xx+kx-1; if ((unsigned)xw>=28u) continue;
                    float vB = rb[yy*28+xw], vD = rd[yy*28+xw];
                    ab += wB[ky*3+kx]*vB;
                    ad += wD[ky*3+kx]*vD;
                }
            }
            bmv = ab;
            dtv = ad + Ap[s];
        }
        // block max over 25 warps
        float m = dtv;
        #pragma unroll
        for (int o=16;o;o>>=1) m = fmaxf(m, __shfl_xor_sync(0xFFFFFFFFu, m, o));
        if ((tid&31)==0) red[tid>>5] = m;
        __syncthreads();
        if (tid < 32){
            float v = (tid<25)? red[tid] : -1e30f;
            #pragma unroll
            for (int o=16;o;o>>=1) v = fmaxf(v, __shfl_xor_sync(0xFFFFFFFFu, v, o));
            if (tid==0) red[0]=v;
        }
        __syncthreads();
        m = red[0];
        __syncthreads();
        float e = (tid<784) ? __expf(dtv - m) : 0.f;
        float sum = e;
        #pragma unroll
        for (int o=16;o;o>>=1) sum += __shfl_xor_sync(0xFFFFFFFFu, sum, o);
        if ((tid&31)==0) red[tid>>5] = sum;
        __syncthreads();
        if (tid < 32){
            float v = (tid<25)? red[tid] : 0.f;
            #pragma unroll
            for (int o=16;o;o>>=1) v += __shfl_xor_sync(0xFFFFFFFFu, v, o);
            if (tid==0) red[0]=v;
        }
        __syncthreads();
        float inv = 1.f/red[0];
        if (tid < 784)
            g_wsl[((size_t)(b*64 + s))*Ll + tid] = e * inv * bmv;
        return;
    }
    // ---- attention for one (b,h) ----
    {
        ulonglong2* KV = (ulonglong2*)pool;          // 784
        ulonglong2* VV = KV + Ll;                    // 784
        int bh = bid - 640;
        size_t base4 = (size_t)bh * Ll;
        if (tid < 784){
            KV[tid] = ((const ulonglong2*)g_kb)[base4 + tid];
            VV[tid] = ((const ulonglong2*)g_vb)[base4 + tid];
        }
        __syncthreads();
        if (tid < 784){
            float4 q = ((const float4*)g_qb)[base4 + tid];
            const float CS = 0.7213475204444817f;
            unsigned long long q01 = pk2(q.x*CS, q.y*CS);
            unsigned long long q23 = pk2(q.z*CS, q.w*CS);
            unsigned long long a01 = pk2(0.f,0.f), a23 = pk2(0.f,0.f);
            float den = 0.f;
            #pragma unroll 4
            for (int j=0; j<Ll; j++){
                ulonglong2 kk = KV[j];
                ulonglong2 vv = VV[j];
                unsigned long long pr = fma2(q23, kk.y, mul2(q01, kk.x));
                float lo, hi; upk2(pr, lo, hi);
                float s = lo + hi;
                float e; asm("ex2.approx.f32 %0, %1;" : "=f"(e) : "f"(s));
                unsigned long long ee = pk2(e, e);
                a01 = fma2(ee, vv.x, a01);
                a23 = fma2(ee, vv.y, a23);
                den += e;
            }
            float inv = __frcp_rn(den);
            float a0,a1,a2,a3;
            upk2(a01,a0,a1); upk2(a23,a2,a3);
            int b = bh/16, hh = bh%16;
            float4 r; r.x=a0*inv; r.y=a1*inv; r.z=a2*inv; r.w=a3*inv;
            ((float4*)g_ob)[(((size_t)b*Ll + tid)*64 + hh*4)/4] = r;
        }
    }
}

// =======================================================================
// STAGE C (512 thr): dw7b | ssd tail (h+hz+Cm-dw3+x3) | proj
// grid: [0,784) dw7b, [784,792) ssd, [792,920) proj
// =======================================================================
__global__ void __launch_bounds__(512,1)
k_stageC(const float* __restrict__ x,
         const float* __restrict__ dw2_w, const float* __restrict__ dw2_b,
         const float* __restrict__ hzw, const float* __restrict__ outw,
         const float* __restrict__ Dp, const float* __restrict__ ssd_dw,
         const float* __restrict__ pw, const float* __restrict__ bn4){
    extern __shared__ float pool[];
    int tid = threadIdx.x;
    int bid = blockIdx.x;

    if (bid < 784){
        // ---- dw7b ----
        int idx = bid*512 + tid;
        int p = idx % Ll; int c = (idx/Ll) % Cc; int b = idx/(Ll*Cc);
        int y = p/28, xx = p%28;
        const float* ip = g_x1g + ((size_t)(b*Cc + c))*Ll;
        const float* wc = dw2_w + c*49;
        float acc = dw2_b[c];
        #pragma unroll
        for (int ky=0; ky<7; ky++){
            int yy = y+ky-3; if ((unsigned)yy >= 28u) continue;
            #pragma unroll
            for (int kx=0; kx<7; kx++){
                int xw = xx+kx-3; if ((unsigned)xw >= 28u) continue;
                acc += wc[ky*7+kx] * ip[yy*28+xw];
            }
        }
        g_b1[idx] = acc;
        return;
    }
    if (bid < 792){
        // ---- SSD tail for one batch ----
        float* wbuf = pool;            // 8320  (128*65)
        float* zbuf = pool + 8320;     // 8320
        float* shh  = pool + 16640;    // 4224  (64*66)
        float* h2b  = pool + 20864;    // 4224
        int b = bid - 784;
        // phase1: h[c][s] = sum_l x3[c,l] * wsl[s,l]
        int cg = tid & 15, sg = tid >> 4;    // 16 x 32
        int c0 = cg*4, s0 = sg*2;
        float hacc[4][2] = {};
        for (int ch=0; ch<8; ch++){
            int l0 = ch*98;
            for (int i=tid; i<64*98; i+=512){
                int c=i/98, l=i%98;
                wbuf[c*99+l] = x[((size_t)(b*DIMc + 128 + c))*Ll + l0 + l];
            }
            for (int i=tid; i<64*98; i+=512){
                int s=i/98, l=i%98;
                zbuf[s*99+l] = g_wsl[((size_t)(b*64 + s))*Ll + l0 + l];
            }
            __syncthreads();
            #pragma unroll 2
            for (int l=0; l<98; l++){
                float w0 = zbuf[s0*99+l], w1 = zbuf[(s0+1)*99+l];
                #pragma unroll
                for (int k=0;k<4;k++){
                    float xc = wbuf[(c0+k)*99+l];
                    hacc[k][0] += xc*w0;
                    hacc[k][1] += xc*w1;
                }
            }
            __syncthreads();
        }
        #pragma unroll
        for (int k=0;k<4;k++){
            shh[(c0+k)*66 + s0]     = hacc[k][0];
            shh[(c0+k)*66 + s0 + 1] = hacc[k][1];
        }
        // phase2a: zv[o][s] = hzw[o,:] @ h[:,s]
        for (int i=tid; i<128*64; i+=512) wbuf[(i/64)*65 + (i%64)] = hzw[i];
        __syncthreads();
        for (int i=tid; i<128*64; i+=512){
            int o=i/64, s=i%64;
            float acc = 0.f;
            const float* wr = wbuf + o*65;
            #pragma unroll 8
            for (int c=0;c<64;c++) acc += wr[c]*shh[c*66+s];
            zbuf[o*65+s] = acc;
        }
        __syncthreads();
        // phase2b: gate gs[c][s] into shh (overwrite)
        float Dv = Dp[0];
        for (int i=tid; i<64*64; i+=512){
            int c=i/64, s=i%64;
            float hv = zbuf[c*65+s], z = zbuf[(64+c)*65+s];
            shh[c*66+s] = hv * (z/(1.f+__expf(-z))) + hv*Dv;
        }
        __syncthreads();
        // phase2c: h2[o][s] = outw[o,:] @ gs[:,s]
        for (int i=tid; i<64*64; i+=512) wbuf[(i/64)*65 + (i%64)] = outw[i];
        __syncthreads();
        for (int i=tid; i<64*64; i+=512){
            int o=i/64, s=i%64;
            float acc = 0.f;
            const float* wr = wbuf + o*65;
            #pragma unroll 8
            for (int c=0;c<64;c++) acc += wr[c]*shh[c*66+s];
            h2b[o*66+s] = acc;
        }
        __syncthreads();
        // phase3: per 4-row chunk, Cm = dw3(bcdt1[64+s]); b3 = h2 @ Cm
        for (int rc=0; rc<7; rc++){
            int p0 = rc*112;
            for (int i=tid; i<64*112; i+=512){
                int s=i/112, lo=i%112;
                int p = p0+lo; int y=p/28, xx=p%28;
                const float* ip = g_bcdt1 + ((size_t)(b*192 + 64 + s))*Ll;
                const float* wc = ssd_dw + (64+s)*9;
                float acc = 0.f;
                #pragma unroll
                for (int ky=0; ky<3; ky++){
                    int yy=y+ky-1; if ((unsigned)yy>=28u) continue;
                    #pragma unroll
                    for (int kx=0; kx<3; kx++){
                        int xw=xx+kx-1; if ((unsigned)xw>=28u) continue;
                        acc += wc[ky*3+kx]*ip[yy*28+xw];
                    }
                }
                wbuf[s*113+lo] = acc;
            }
            __syncthreads();
            for (int i=tid; i<64*112; i+=512){
                int c=i/112, lo=i%112;
                float acc = 0.f;
                const float* hr = h2b + c*66;
                #pragma unroll 8
                for (int s=0;s<64;s++) acc += hr[s]*wbuf[s*113+lo];
                g_b3[((size_t)(b*64 + c))*Ll + p0+lo] = acc;
            }
            __syncthreads();
        }
        return;
    }
    // ---- proj + residual + BN ----
    {
        float* sw  = pool;            // 64*65
        float* sx  = pool + 64*65;    // 64*49
        float* sbn = pool + 64*65 + 64*PT;   // 256
        int bidL = bid - 792;
        int b = bidL / NTt, p0 = (bidL % NTt) * PT;
        for (int i=tid; i<64*64; i+=512){ sw[(i/64)*65 + (i%64)] = pw[i]; }
        for (int i=tid; i<256; i+=512) sbn[i] = bn4[i];
        for (int i=tid; i<64*PT; i+=512){
            int c=i%64, px=i/64;
            sx[c*PT+px] = g_ob[((size_t)b*Ll + p0+px)*64 + c];
        }
        __syncthreads();
        for (int i=tid; i<64*PT; i+=512){
            int o=i/PT, px=i%PT;
            float acc = 0.f;
            const float* wr = sw + o*65;
            #pragma unroll 8
            for (int j=0;j<64;j++) acc += wr[j]*sx[j*PT+px];
            float xv = x[((size_t)(b*DIMc + 192 + o))*Ll + p0+px];
            g_b4[((size_t)(b*64+o))*Ll + p0+px] = bnf(xv + acc, sbn, o, 64);
        }
    }
}

// =======================================================================
// STAGE D (256 thr): fused mlp1 + mlp2 (chunked weights)
// =======================================================================
__global__ void __launch_bounds__(256,1)
k_stageD(const float* __restrict__ x,
         const float* __restrict__ w1, const float* __restrict__ bn_m,
         const float* __restrict__ w2, const float* __restrict__ bn1,
         float* __restrict__ out){
    extern __shared__ float pool[];
    float* wb  = pool;                 // 256*65 = 16640
    float* sx  = pool + 16640;         // 256*49 = 12544
    float* sm1 = pool + 29184;         // 128*49 = 6272
    int b = blockIdx.x / NTt, p0 = (blockIdx.x % NTt) * PT;
    int tid = threadIdx.x;
    for (int i=tid; i<256*PT; i+=256){
        int c=i/PT, px=i%PT;
        const float* src = (c<64) ? g_b1 : (c<128) ? g_b2 : (c<192) ? g_b3 : g_b4;
        sx[i] = src[((size_t)(b*64 + (c&63)))*Ll + p0+px];
    }
    // phase 1: m1 = relu(bn(w1 @ xa))
    int og = tid % 32, pg = tid / 32;      // 32 x 8
    int o0 = og*4, px0 = pg*7;
    int cnt = PT - px0; if (cnt > 7) cnt = 7; if (cnt < 0) cnt = 0;
    float acc[4][7];
    #pragma unroll
    for (int k=0;k<4;k++)
        #pragma unroll
        for (int j=0;j<7;j++) acc[k][j]=0.f;
    for (int ci=0; ci<4; ci++){
        __syncthreads();
        for (int i=tid; i<128*64; i+=256){
            int o=i/64, c=i%64;
            wb[o*65+c] = w1[o*256 + ci*64 + c];
        }
        __syncthreads();
        if (cnt > 0){
            for (int c=0;c<64;c++){
                float v0=wb[(o0+0)*65+c], v1=wb[(o0+1)*65+c], v2=wb[(o0+2)*65+c], v3=wb[(o0+3)*65+c];
                #pragma unroll 7
                for (int j=0;j<7;j++){
                    if (j<cnt){
                        float xx = sx[(ci*64+c)*PT + px0 + j];
                        acc[0][j]+=v0*xx; acc[1][j]+=v1*xx; acc[2][j]+=v2*xx; acc[3][j]+=v3*xx;
                    }
                }
            }
        }
    }
    #pragma unroll
    for (int k=0;k<4;k++)
        for (int j=0;j<cnt;j++){
            float v = bnf(acc[k][j], bn_m, o0+k, 128);
            sm1[(o0+k)*PT + px0+j] = fmaxf(v, 0.f);
        }
    // phase 2: out = x + bn(w2 @ m1)
    int og2 = tid % 64, pg2 = tid / 64;    // 64 x 4
    int q0 = og2*4, qx0 = pg2*13;
    int cnt2 = PT - qx0; if (cnt2 > 13) cnt2 = 13; if (cnt2 < 0) cnt2 = 0;
    float ac2[4][13];
    #pragma unroll
    for (int k=0;k<4;k++)
        #pragma unroll
        for (int j=0;j<13;j++) ac2[k][j]=0.f;
    for (int cj=0; cj<2; cj++){
        __syncthreads();
        for (int i=tid; i<256*64; i+=256){
            int o=i/64, c=i%64;
            wb[o*65+c] = w2[o*128 + cj*64 + c];
        }
        __syncthreads();
        if (cnt2 > 0){
            for (int c=0;c<64;c++){
                float v0=wb[(q0+0)*65+c], v1=wb[(q0+1)*65+c], v2=wb[(q0+2)*65+c], v3=wb[(q0+3)*65+c];
                #pragma unroll 13
                for (int j=0;j<13;j++){
                    if (j<cnt2){
                        float xx = sm1[(cj*64+c)*PT + qx0 + j];
                        ac2[0][j]+=v0*xx; ac2[1][j]+=v1*xx; ac2[2][j]+=v2*xx; ac2[3][j]+=v3*xx;
                    }
                }
            }
        }
    }
    #pragma unroll
    for (int k=0;k<4;k++)
        for (int j=0;j<cnt2;j++){
            size_t idx = ((size_t)(b*DIMc + q0+k))*Ll + p0+qx0+j;
            out[idx] = x[idx] + bnf(ac2[k][j], bn1, q0+k, 256);
        }
}

// ---------------- launch ----------------
extern "C" void kernel_launch(void* const* d_in, const int* in_sizes, int n_in,
                              void* d_out, int out_size){
    const float* x       = (const float*)d_in[0];
    const float* dw1_w   = (const float*)d_in[1];
    const float* dw1_b   = (const float*)d_in[2];
    const float* bn_dw1  = (const float*)d_in[3];
    const float* f1_w    = (const float*)d_in[4];
    const float* f1_b    = (const float*)d_in[5];
    const float* f2_w    = (const float*)d_in[6];
    const float* f2_b    = (const float*)d_in[7];
    const float* g_w     = (const float*)d_in[8];
    const float* g_b     = (const float*)d_in[9];
    const float* bn_g    = (const float*)d_in[10];
    const float* dw2_w   = (const float*)d_in[11];
    const float* dw2_b   = (const float*)d_in[12];
    const float* hatt1_w = (const float*)d_in[13];
    const float* vatt1_w = (const float*)d_in[14];
    const float* hatt2_w = (const float*)d_in[15];
    const float* vatt2_w = (const float*)d_in[16];
    const float* bn_mra  = (const float*)d_in[17];
    const float* bcdt_w  = (const float*)d_in[18];
    const float* ssd_dw_w= (const float*)d_in[19];
    const float* hz_w    = (const float*)d_in[20];
    const float* out_w   = (const float*)d_in[21];
    const float* A_param = (const float*)d_in[22];
    const float* D_param = (const float*)d_in[23];
    const float* qkv_w   = (const float*)d_in[24];
    const float* proj_w  = (const float*)d_in[25];
    const float* bn_n4   = (const float*)d_in[26];
    const float* mlp1_w  = (const float*)d_in[27];
    const float* bn_mlp  = (const float*)d_in[28];
    const float* mlp2_w  = (const float*)d_in[29];
    const float* bn_n1   = (const float*)d_in[30];
    float* out = (float*)d_out;
    (void)n_in; (void)in_sizes; (void)out_size;

    const int SM_A = (192*65 + 64*PT) * 4;                       // 62464
    const int SM_B = (3136 + 6272 + 8192) * 4;                   // 70400
    const int SM_C = (8320 + 8320 + 4224 + 4224) * 4;            // 100352
    const int SM_D = (16640 + 12544 + 6272) * 4;                 // 141824

    cudaFuncSetAttribute(k_stageA, cudaFuncAttributeMaxDynamicSharedMemorySize, SM_A);
    cudaFuncSetAttribute(k_stageB, cudaFuncAttributeMaxDynamicSharedMemorySize, SM_B);
    cudaFuncSetAttribute(k_stageC, cudaFuncAttributeMaxDynamicSharedMemorySize, SM_C);
    cudaFuncSetAttribute(k_stageD, cudaFuncAttributeMaxDynamicSharedMemorySize, SM_D);

    k_stageA<<<2336, 256, SM_A>>>(x, dw1_w, dw1_b, bn_dw1,
                                  hatt1_w, vatt1_w, hatt2_w, vatt2_w, bn_mra,
                                  bcdt_w, qkv_w);
    k_stageB<<<768, 800, SM_B>>>(f1_w, f1_b, f2_w, f2_b, g_w, g_b, bn_g,
                                 ssd_dw_w, A_param);
    k_stageC<<<920, 512, SM_C>>>(x, dw2_w, dw2_b, hz_w, out_w, D_param,
                                 ssd_dw_w, proj_w, bn_n4);
    k_stageD<<<128, 256, SM_D>>>(x, mlp1_w, bn_mlp, mlp2_w, bn_n1, out);
}

// round 12
// speedup vs baseline: 1.3332x; 1.3332x over previous
#include <cuda_runtime.h>
#include <math.h>

#define Bq 8
#define Cc 64
#define Ll 784
#define HIDd 128
#define Sdim 64
#define NHh 16
#define DIMc 256
#define PT 49
#define NTt 16

// ---------------- scratch ----------------
__device__ float g_x1o [Bq*Cc*Ll];
__device__ float g_x1g [Bq*Cc*Ll];
__device__ float g_b1  [Bq*Cc*Ll];
__device__ float g_b2  [Bq*Cc*Ll];
__device__ float g_bcdt1[Bq*192*Ll];
__device__ float g_wsl [Bq*Sdim*Ll];
__device__ float g_h2  [Bq*Cc*Sdim];
__device__ float g_b3  [Bq*Cc*Ll];
__device__ float g_qb  [Bq*NHh*Ll*4];
__device__ float g_kb  [Bq*NHh*Ll*4];
__device__ float g_vb  [Bq*NHh*Ll*4];
__device__ float g_ob  [Bq*Ll*Cc];
__device__ float g_b4  [Bq*Cc*Ll];
__device__ float g_m1  [Bq*HIDd*Ll];

__device__ __forceinline__ float bnf(float x, const float* __restrict__ p, int c, int C){
    return (x - p[2*C+c]) * p[c] * rsqrtf(p[3*C+c] + 1e-5f) + p[C+c];
}

__device__ __forceinline__ unsigned long long pk2(float a, float b){
    unsigned long long r; asm("mov.b64 %0, {%1,%2};" : "=l"(r) : "f"(a), "f"(b)); return r;
}
__device__ __forceinline__ void upk2(unsigned long long v, float& a, float& b){
    asm("mov.b64 {%0,%1}, %2;" : "=f"(a), "=f"(b) : "l"(v));
}
__device__ __forceinline__ unsigned long long fma2(unsigned long long a, unsigned long long b, unsigned long long c){
    unsigned long long r; asm("fma.rn.f32x2 %0, %1, %2, %3;" : "=l"(r) : "l"(a), "l"(b), "l"(c)); return r;
}
__device__ __forceinline__ unsigned long long mul2(unsigned long long a, unsigned long long b){
    unsigned long long r; asm("mul.rn.f32x2 %0, %1, %2;" : "=l"(r) : "l"(a), "l"(b)); return r;
}

// =======================================================================
// STAGE A (256 thr): dw7a | att2 | bcdt | qkv   (unchanged from R11)
// =======================================================================
__global__ void __launch_bounds__(256,1)
k_stageA(const float* __restrict__ x,
         const float* __restrict__ dw1_w, const float* __restrict__ dw1_b,
         const float* __restrict__ bn_dw1,
         const float* __restrict__ wh1, const float* __restrict__ wv1,
         const float* __restrict__ wh2, const float* __restrict__ wv2,
         const float* __restrict__ bnm,
         const float* __restrict__ bcdt_w, const float* __restrict__ qkv_w){
    extern __shared__ float pool[];
    int tid = threadIdx.x;
    int bid = blockIdx.x;

    if (bid < 1568){
        int idx = bid*256 + tid;
        int p = idx % Ll; int c = (idx/Ll) % Cc; int b = idx/(Ll*Cc);
        int y = p/28, xx = p%28;
        const float* ip = x + ((size_t)(b*DIMc + c))*Ll;
        const float* wc = dw1_w + c*49;
        float acc = dw1_b[c];
        #pragma unroll
        for (int ky=0; ky<7; ky++){
            int yy = y+ky-3; if ((unsigned)yy >= 28u) continue;
            #pragma unroll
            for (int kx=0; kx<7; kx++){
                int xw = xx+kx-3; if ((unsigned)xw >= 28u) continue;
                acc += wc[ky*7+kx] * ip[yy*28+xw];
            }
        }
        g_x1o[idx] = bnf(acc, bn_dw1, c, Cc);
        return;
    }
    if (bid < 2080){
        float* mp   = pool;
        float* xt   = pool + 784;
        float* sacc = pool + 884;
        float* sh   = pool + 984;
        float* cbuf = pool + 1174;
        float* sw1  = pool + 1364;
        float* sw2  = pool + 1397;
        float* sw3  = pool + 1430;
        float* sw4  = pool + 1463;
        int bc = bid - 1568; int b = bc/64, c = bc%64;
        if (tid < 33){ sw1[tid]=wh1[c*33+tid]; sw2[tid]=wv1[c*33+tid];
                       sw3[tid]=wh2[c*33+tid]; sw4[tid]=wv2[c*33+tid]; }
        const float* x2 = x + ((size_t)(b*DIMc + 64 + c))*Ll;
        for (int p=tid; p<784; p+=256){
            int y=p/28, xx=p%28;
            float m = -1e30f;
            #pragma unroll
            for (int dy=-1; dy<=1; dy++){ int yy=y+dy; if ((unsigned)yy>=28u) continue;
                #pragma unroll
                for (int dx=-1; dx<=1; dx++){ int xw=xx+dx; if ((unsigned)xw>=28u) continue;
                    m = fmaxf(m, x2[yy*28+xw]); } }
            mp[p] = m;
        }
        __syncthreads();
        if (tid < 100){
            int oy = tid/10, ox = tid%10;
            const float fa[4] = {1.f,3.f,3.f,1.f};
            float acc = 0.f;
            #pragma unroll
            for (int ty=0; ty<4; ty++){
                int q = 3*oy + ty - 1; if (q < 0) q = -q; if (q >= 28) q = 54 - q;
                #pragma unroll
                for (int tx=0; tx<4; tx++){
                    int r = 3*ox + tx - 1; if (r < 0) r = -r; if (r >= 28) r = 54 - r;
                    acc += fa[ty]*fa[tx]*mp[q*28+r];
                }
            }
            xt[tid] = acc * (1.0f/64.0f);
        }
        __syncthreads();
        if (tid < 100){
            int y = tid/10, xo = tid%10;
            float s = 0.f;
            #pragma unroll
            for (int ky=0; ky<11; ky++){ int yy=y+ky-5; if ((unsigned)yy>=10u) continue;
                #pragma unroll
                for (int kx=0; kx<3; kx++){ int xx=xo+kx-1; if ((unsigned)xx>=10u) continue;
                    s += sw1[ky*3+kx]*xt[yy*10+xx]; } }
            #pragma unroll
            for (int ky=0; ky<3; ky++){ int yy=y+ky-1; if ((unsigned)yy>=10u) continue;
                #pragma unroll
                for (int kx=0; kx<11; kx++){ int xx=xo+kx-5; if ((unsigned)xx>=10u) continue;
                    s += sw2[ky*11+kx]*xt[yy*10+xx]; } }
            sacc[tid] = s;
        }
        if (tid < 190){
            int r = tid/19, j = tid%19, d = j - r;
            sh[tid] = (d >= 0 && d < 10) ? xt[r*10 + d] : 0.f;
        }
        __syncthreads();
        if (tid < 190){
            int u = tid/19, v = tid%19;
            float s = 0.f;
            #pragma unroll
            for (int ky=0; ky<11; ky++){ int uu=u+ky-5; if ((unsigned)uu>=10u) continue;
                #pragma unroll
                for (int kx=0; kx<3; kx++){ int vv=v+kx-1; if ((unsigned)vv>=19u) continue;
                    s += sw3[ky*3+kx]*sh[uu*19+vv]; } }
            cbuf[tid] = s;
        }
        __syncthreads();
        if (tid < 100){
            int y = tid/10, xo = tid%10;
            sacc[tid] += cbuf[20*y + xo];
        }
        __syncthreads();
        if (tid < 190){
            int a = tid/10, b2 = tid%10, d = a - b2;
            sh[tid] = (d >= 0 && d < 10) ? xt[d*10 + b2] : 0.f;
        }
        __syncthreads();
        if (tid < 190){
            int a = tid/10, b2 = tid%10;
            float s = 0.f;
            #pragma unroll
            for (int ky=0; ky<3; ky++){ int av=a+ky-1; if ((unsigned)av>=19u) continue;
                #pragma unroll
                for (int kx=0; kx<11; kx++){ int bv=b2+kx-5; if ((unsigned)bv>=10u) continue;
                    s += sw4[ky*11+kx]*sh[av*10+bv]; } }
            cbuf[tid] = s;
        }
        __syncthreads();
        if (tid < 100){
            int y = tid/10, xo = tid%10;
            int g = 20*xo + y;
            float s = sacc[tid] + cbuf[(g%19)*10 + (g/19)];
            s = bnf(s, bnm, c, 64);
            sacc[tid] = 1.f/(1.f + __expf(-s));
        }
        __syncthreads();
        float* op = g_b2 + (size_t)bc*Ll;
        for (int p=tid; p<Ll; p+=256){
            int y = p/28, xx = p%28;
            op[p] = x2[p] * sacc[(y*10/28)*10 + (xx*10/28)];
        }
        return;
    }
    {
        int isQ = (bid >= 2208);
        int bidL = bid - (isQ ? 2208 : 2080);
        const float* w = isQ ? qkv_w : bcdt_w;
        int chOff = isQ ? 192 : 128;
        float* sw = pool;
        float* sx = pool + 192*65;
        int b = bidL / NTt, p0 = (bidL % NTt) * PT;
        for (int i=tid; i<192*64; i+=256){ sw[(i/64)*65 + (i%64)] = w[i]; }
        for (int i=tid; i<64*PT; i+=256){
            int c=i/PT, px=i%PT;
            sx[i] = x[((size_t)(b*DIMc + chOff + c))*Ll + p0+px];
        }
        __syncthreads();
        int og = tid % 48, pg = tid / 48;
        int o0 = og*4, px0 = pg*10;
        int cnt = PT - px0; if (cnt > 10) cnt = 10; if (cnt < 0) cnt = 0;
        float acc[4][10];
        #pragma unroll
        for (int k=0;k<4;k++)
            #pragma unroll
            for (int j=0;j<10;j++) acc[k][j]=0.f;
        if (cnt > 0){
            for (int c=0;c<64;c++){
                float w0=sw[(o0+0)*65+c], w1=sw[(o0+1)*65+c], w2=sw[(o0+2)*65+c], w3=sw[(o0+3)*65+c];
                #pragma unroll 10
                for (int j=0;j<10;j++){
                    if (j<cnt){
                        float xx = sx[c*PT + px0 + j];
                        acc[0][j]+=w0*xx; acc[1][j]+=w1*xx; acc[2][j]+=w2*xx; acc[3][j]+=w3*xx;
                    }
                }
            }
            if (!isQ){
                #pragma unroll
                for (int k=0;k<4;k++)
                    for (int j=0;j<cnt;j++)
                        g_bcdt1[((size_t)(b*192 + o0+k))*Ll + p0+px0+j] = acc[k][j];
            } else {
                #pragma unroll
                for (int k=0;k<4;k++){
                    int o = o0+k;
                    int part = o/64, rem = o%64, hh = rem/4, dd = rem%4;
                    float* dst = (part==0) ? g_qb : (part==1) ? g_kb : g_vb;
                    for (int j=0;j<cnt;j++)
                        dst[(((size_t)b*16 + hh)*Ll + p0+px0+j)*4 + dd] = acc[k][j];
                }
            }
        }
    }
}

// =======================================================================
// STAGE B (800 thr): star | softAB(dw3 fused) | attn   (unchanged from R11)
// =======================================================================
__global__ void __launch_bounds__(800,1)
k_stageB(const float* __restrict__ f1w, const float* __restrict__ f1b,
         const float* __restrict__ f2w, const float* __restrict__ f2b,
         const float* __restrict__ gw,  const float* __restrict__ gb,
         const float* __restrict__ bng,
         const float* __restrict__ ssd_dw, const float* __restrict__ Ap){
    extern __shared__ float pool[];
    int tid = threadIdx.x;
    int bid = blockIdx.x;

    if (bid < 128){
        float* sxv = pool;
        float* sa  = pool + 3136;
        float* wb  = pool + 9408;
        int b = bid/16, p0 = (bid%16)*PT;
        for (int i=tid; i<64*PT; i+=800){
            int c=i/PT, px=i%PT;
            sxv[i] = g_x1o[((size_t)(b*64+c))*Ll + p0+px];
        }
        for (int i=tid; i<8192; i+=800) wb[i] = f1w[i];
        __syncthreads();
        for (int i=tid; i<128*PT; i+=800){
            int h=i/PT, px=i%PT;
            float a = f1b[h];
            const float* wr = wb + h*64;
            #pragma unroll 8
            for (int c=0;c<64;c++) a += wr[c]*sxv[c*PT+px];
            sa[i] = a;
        }
        __syncthreads();
        for (int i=tid; i<8192; i+=800) wb[i] = f2w[i];
        __syncthreads();
        for (int i=tid; i<128*PT; i+=800){
            int h=i/PT, px=i%PT;
            float a2 = f2b[h];
            const float* wr = wb + h*64;
            #pragma unroll 8
            for (int c=0;c<64;c++) a2 += wr[c]*sxv[c*PT+px];
            float a1 = fminf(fmaxf(sa[i],0.f),6.f);
            sa[i] = a1*a2;
        }
        __syncthreads();
        for (int i=tid; i<8192; i+=800) wb[i] = gw[i];
        __syncthreads();
        for (int i=tid; i<64*PT; i+=800){
            int o=i/PT, px=i%PT;
            float acc = gb[o];
            const float* wr = wb + o*128;
            #pragma unroll 8
            for (int j=0;j<128;j++) acc += wr[j]*sa[j*PT+px];
            g_x1g[((size_t)(b*64+o))*Ll + p0+px] = bnf(acc, bng, o, 64);
        }
        return;
    }
    if (bid < 640){
        float* rb  = pool;
        float* rd  = pool + 784;
        float* red = pool + 1568;
        int bs = bid - 128; int b = bs/64, s = bs%64;
        for (int i=tid; i<784; i+=800){
            rb[i] = g_bcdt1[((size_t)(b*192 + s))*Ll + i];
            rd[i] = g_bcdt1[((size_t)(b*192 + 128 + s))*Ll + i];
        }
        __syncthreads();
        float dtv = -1e30f, bmv = 0.f;
        if (tid < 784){
            int y = tid/28, xx = tid%28;
            const float* wB = ssd_dw + s*9;
            const float* wD = ssd_dw + (128+s)*9;
            float ab = 0.f, ad = 0.f;
            #pragma unroll
            for (int ky=0; ky<3; ky++){
                int yy=y+ky-1; if ((unsigned)yy>=28u) continue;
                #pragma unroll
                for (int kx=0; kx<3; kx++){
                    int xw=xx+kx-1; if ((unsigned)xw>=28u) continue;
                    float vB = rb[yy*28+xw], vD = rd[yy*28+xw];
                    ab += wB[ky*3+kx]*vB;
                    ad += wD[ky*3+kx]*vD;
                }
            }
            bmv = ab;
            dtv = ad + Ap[s];
        }
        float m = dtv;
        #pragma unroll
        for (int o=16;o;o>>=1) m = fmaxf(m, __shfl_xor_sync(0xFFFFFFFFu, m, o));
        if ((tid&31)==0) red[tid>>5] = m;
        __syncthreads();
        if (tid < 32){
            float v = (tid<25)? red[tid] : -1e30f;
            #pragma unroll
            for (int o=16;o;o>>=1) v = fmaxf(v, __shfl_xor_sync(0xFFFFFFFFu, v, o));
            if (tid==0) red[0]=v;
        }
        __syncthreads();
        m = red[0];
        __syncthreads();
        float e = (tid<784) ? __expf(dtv - m) : 0.f;
        float sum = e;
        #pragma unroll
        for (int o=16;o;o>>=1) sum += __shfl_xor_sync(0xFFFFFFFFu, sum, o);
        if ((tid&31)==0) red[tid>>5] = sum;
        __syncthreads();
        if (tid < 32){
            float v = (tid<25)? red[tid] : 0.f;
            #pragma unroll
            for (int o=16;o;o>>=1) v += __shfl_xor_sync(0xFFFFFFFFu, v, o);
            if (tid==0) red[0]=v;
        }
        __syncthreads();
        float inv = 1.f/red[0];
        if (tid < 784)
            g_wsl[((size_t)(b*64 + s))*Ll + tid] = e * inv * bmv;
        return;
    }
    {
        ulonglong2* KV = (ulonglong2*)pool;
        ulonglong2* VV = KV + Ll;
        int bh = bid - 640;
        size_t base4 = (size_t)bh * Ll;
        if (tid < 784){
            KV[tid] = ((const ulonglong2*)g_kb)[base4 + tid];
            VV[tid] = ((const ulonglong2*)g_vb)[base4 + tid];
        }
        __syncthreads();
        if (tid < 784){
            float4 q = ((const float4*)g_qb)[base4 + tid];
            const float CS = 0.7213475204444817f;
            unsigned long long q01 = pk2(q.x*CS, q.y*CS);
            unsigned long long q23 = pk2(q.z*CS, q.w*CS);
            unsigned long long a01 = pk2(0.f,0.f), a23 = pk2(0.f,0.f);
            float den = 0.f;
            #pragma unroll 4
            for (int j=0; j<Ll; j++){
                ulonglong2 kk = KV[j];
                ulonglong2 vv = VV[j];
                unsigned long long pr = fma2(q23, kk.y, mul2(q01, kk.x));
                float lo, hi; upk2(pr, lo, hi);
                float s = lo + hi;
                float e; asm("ex2.approx.f32 %0, %1;" : "=f"(e) : "f"(s));
                unsigned long long ee = pk2(e, e);
                a01 = fma2(ee, vv.x, a01);
                a23 = fma2(ee, vv.y, a23);
                den += e;
            }
            float inv = __frcp_rn(den);
            float a0,a1,a2,a3;
            upk2(a01,a0,a1); upk2(a23,a2,a3);
            int b = bh/16, hh = bh%16;
            float4 r; r.x=a0*inv; r.y=a1*inv; r.z=a2*inv; r.w=a3*inv;
            ((float4*)g_ob)[(((size_t)b*Ll + tid)*64 + hh*4)/4] = r;
        }
    }
}

// =======================================================================
// STAGE C (512 thr): dw7b [0,784) | ssd h+hz [784,800) | proj [800,928)
// =======================================================================
__global__ void __launch_bounds__(512,1)
k_stageC(const float* __restrict__ x,
         const float* __restrict__ dw2_w, const float* __restrict__ dw2_b,
         const float* __restrict__ hzw, const float* __restrict__ outw,
         const float* __restrict__ Dp,
         const float* __restrict__ pw, const float* __restrict__ bn4){
    extern __shared__ float pool[];
    int tid = threadIdx.x;
    int bid = blockIdx.x;

    if (bid < 784){
        int idx = bid*512 + tid;
        int p = idx % Ll; int c = (idx/Ll) % Cc; int b = idx/(Ll*Cc);
        int y = p/28, xx = p%28;
        const float* ip = g_x1g + ((size_t)(b*Cc + c))*Ll;
        const float* wc = dw2_w + c*49;
        float acc = dw2_b[c];
        #pragma unroll
        for (int ky=0; ky<7; ky++){
            int yy = y+ky-3; if ((unsigned)yy >= 28u) continue;
            #pragma unroll
            for (int kx=0; kx<7; kx++){
                int xw = xx+kx-3; if ((unsigned)xw >= 28u) continue;
                acc += wc[ky*7+kx] * ip[yy*28+xw];
            }
        }
        g_b1[idx] = acc;
        return;
    }
    if (bid < 800){
        // ---- SSD h + hz for (b, s-half): fully self-contained over 32 s-columns
        float* sxb = pool;                 // 64*99 = 6336
        float* swl = pool + 6336;          // 32*99 = 3168
        float* shh = pool + 9504;          // 64*33 = 2112
        float* wz  = pool + 11616;         // 128*65 = 8320
        float* zz  = pool + 19936;         // 128*33 = 4224
        int bb = bid - 784;
        int b = bb >> 1, sh = bb & 1;
        // phase1: h[c][s] = sum_l x3[c,l] * wsl[sh*32+s, l]
        int c0 = (tid & 15)*4, s0 = tid >> 4;   // 16 c-groups x 32 s
        float hacc[4] = {0.f,0.f,0.f,0.f};
        for (int ch=0; ch<8; ch++){
            int l0 = ch*98;
            for (int i=tid; i<64*98; i+=512){
                int c=i/98, l=i%98;
                sxb[c*99+l] = x[((size_t)(b*DIMc + 128 + c))*Ll + l0 + l];
            }
            for (int i=tid; i<32*98; i+=512){
                int sr=i/98, l=i%98;
                swl[sr*99+l] = g_wsl[((size_t)(b*64 + sh*32 + sr))*Ll + l0 + l];
            }
            __syncthreads();
            #pragma unroll 2
            for (int l=0; l<98; l++){
                float w0 = swl[s0*99+l];
                #pragma unroll
                for (int k=0;k<4;k++) hacc[k] += sxb[(c0+k)*99+l]*w0;
            }
            __syncthreads();
        }
        #pragma unroll
        for (int k=0;k<4;k++) shh[(c0+k)*33 + s0] = hacc[k];
        // phase2a: zz[o][s] = hzw[o,:] @ h[:,s]
        for (int i=tid; i<128*64; i+=512) wz[(i/64)*65 + (i%64)] = hzw[i];
        __syncthreads();
        for (int i=tid; i<128*32; i+=512){
            int o=i/32, s=i%32;
            float acc = 0.f;
            const float* wr = wz + o*65;
            #pragma unroll 8
            for (int c=0;c<64;c++) acc += wr[c]*shh[c*33+s];
            zz[o*33+s] = acc;
        }
        __syncthreads();
        // phase2b: gate -> sxb[c*33+s]
        float Dv = Dp[0];
        for (int i=tid; i<64*32; i+=512){
            int c=i/32, s=i%32;
            float hv = zz[c*33+s], z = zz[(64+c)*33+s];
            sxb[c*33+s] = hv * (z/(1.f+__expf(-z))) + hv*Dv;
        }
        __syncthreads();
        // phase2c: h2[o][s] = outw[o,:] @ gs[:,s] -> global
        for (int i=tid; i<64*64; i+=512) wz[(i/64)*65 + (i%64)] = outw[i];
        __syncthreads();
        for (int i=tid; i<64*32; i+=512){
            int o=i/32, s=i%32;
            float acc = 0.f;
            const float* wr = wz + o*65;
            #pragma unroll 8
            for (int c=0;c<64;c++) acc += wr[c]*sxb[c*33+s];
            g_h2[((size_t)(b*64 + o))*64 + sh*32 + s] = acc;
        }
        return;
    }
    // ---- proj + residual + BN
    {
        float* sw  = pool;
        float* sx  = pool + 64*65;
        float* sbn = pool + 64*65 + 64*PT;
        int bidL = bid - 800;
        int b = bidL / NTt, p0 = (bidL % NTt) * PT;
        for (int i=tid; i<64*64; i+=512){ sw[(i/64)*65 + (i%64)] = pw[i]; }
        for (int i=tid; i<256; i+=512) sbn[i] = bn4[i];
        for (int i=tid; i<64*PT; i+=512){
            int c=i%64, px=i/64;
            sx[c*PT+px] = g_ob[((size_t)b*Ll + p0+px)*64 + c];
        }
        __syncthreads();
        for (int i=tid; i<64*PT; i+=512){
            int o=i/PT, px=i%PT;
            float acc = 0.f;
            const float* wr = sw + o*65;
            #pragma unroll 8
            for (int j=0;j<64;j++) acc += wr[j]*sx[j*PT+px];
            float xv = x[((size_t)(b*DIMc + 192 + o))*Ll + p0+px];
            g_b4[((size_t)(b*64+o))*Ll + p0+px] = bnf(xv + acc, sbn, o, 64);
        }
    }
}

// =======================================================================
// X3 (512 thr, 56 blocks): Cm = dw3(bcdt1[64+s]); b3 = h2 @ Cm per 112-px chunk
// =======================================================================
__global__ void __launch_bounds__(512,1)
k_x3(const float* __restrict__ ssd_dw){
    extern __shared__ float pool[];
    float* cm  = pool;             // 64*113 = 7232
    float* h2s = pool + 7232;      // 64*65 = 4160
    int b = blockIdx.x / 7, rc = blockIdx.x % 7;
    int p0 = rc*112;
    int tid = threadIdx.x;
    for (int i=tid; i<64*64; i+=512)
        h2s[(i/64)*65 + (i%64)] = g_h2[((size_t)b*64)*64 + i];
    for (int i=tid; i<64*112; i+=512){
        int s=i/112, lo=i%112;
        int p = p0+lo; int y=p/28, xx=p%28;
        const float* ip = g_bcdt1 + ((size_t)(b*192 + 64 + s))*Ll;
        const float* wc = ssd_dw + (64+s)*9;
        float acc = 0.f;
        #pragma unroll
        for (int ky=0; ky<3; ky++){
            int yy=y+ky-1; if ((unsigned)yy>=28u) continue;
            #pragma unroll
            for (int kx=0; kx<3; kx++){
                int xw=xx+kx-1; if ((unsigned)xw>=28u) continue;
                acc += wc[ky*3+kx]*ip[yy*28+xw];
            }
        }
        cm[s*113+lo] = acc;
    }
    __syncthreads();
    for (int i=tid; i<64*112; i+=512){
        int c=i/112, lo=i%112;
        float acc = 0.f;
        const float* hr = h2s + c*65;
        #pragma unroll 8
        for (int s=0;s<64;s++) acc += hr[s]*cm[s*113+lo];
        g_b3[((size_t)(b*64 + c))*Ll + p0+lo] = acc;
    }
}

// =======================================================================
// M1 (256 thr, 512 blocks): mlp1 o-chunk of 32
// =======================================================================
__global__ void __launch_bounds__(256,1)
k_m1(const float* __restrict__ w1, const float* __restrict__ bn_m){
    extern __shared__ float pool[];
    float* sw = pool;              // 32*257 = 8224
    float* sx = pool + 8224;       // 256*49 = 12544
    int b = blockIdx.x >> 6;
    int tile = (blockIdx.x >> 2) & 15;
    int oc = blockIdx.x & 3;
    int p0 = tile*PT;
    int tid = threadIdx.x;
    for (int i=tid; i<32*256; i+=256)
        sw[(i/256)*257 + (i%256)] = w1[(oc*32 + i/256)*256 + (i%256)];
    for (int i=tid; i<256*PT; i+=256){
        int c=i/PT, px=i%PT;
        const float* src = (c<64) ? g_b1 : (c<128) ? g_b2 : (c<192) ? g_b3 : g_b4;
        sx[i] = src[((size_t)(b*64 + (c&63)))*Ll + p0+px];
    }
    __syncthreads();
    int og = tid % 8, pg = tid / 8;    // 8 o-groups x 32 px-groups
    int o0 = og*4, px0 = pg*2;
    int cnt = PT - px0; if (cnt > 2) cnt = 2; if (cnt < 0) cnt = 0;
    float acc[4][2];
    #pragma unroll
    for (int k=0;k<4;k++){ acc[k][0]=0.f; acc[k][1]=0.f; }
    if (cnt > 0){
        for (int c=0;c<256;c++){
            float v0=sw[(o0+0)*257+c], v1=sw[(o0+1)*257+c], v2=sw[(o0+2)*257+c], v3=sw[(o0+3)*257+c];
            float x0 = sx[c*PT + px0];
            float x1 = (cnt>1) ? sx[c*PT + px0 + 1] : 0.f;
            acc[0][0]+=v0*x0; acc[1][0]+=v1*x0; acc[2][0]+=v2*x0; acc[3][0]+=v3*x0;
            acc[0][1]+=v0*x1; acc[1][1]+=v1*x1; acc[2][1]+=v2*x1; acc[3][1]+=v3*x1;
        }
        #pragma unroll
        for (int k=0;k<4;k++)
            for (int j=0;j<cnt;j++){
                int o = oc*32 + o0 + k;
                float v = bnf(acc[k][j], bn_m, o, 128);
                g_m1[((size_t)(b*128 + o))*Ll + p0+px0+j] = fmaxf(v, 0.f);
            }
    }
}

// =======================================================================
// M2 (256 thr, 512 blocks): mlp2 o-chunk of 64 + residual
// =======================================================================
__global__ void __launch_bounds__(256,1)
k_m2(const float* __restrict__ x, const float* __restrict__ w2,
     const float* __restrict__ bn1, float* __restrict__ out){
    extern __shared__ float pool[];
    float* sw = pool;              // 64*129 = 8256
    float* sx = pool + 8256;       // 128*49 = 6272
    int b = blockIdx.x >> 6;
    int tile = (blockIdx.x >> 2) & 15;
    int oc = blockIdx.x & 3;
    int p0 = tile*PT;
    int tid = threadIdx.x;
    for (int i=tid; i<64*128; i+=256)
        sw[(i/128)*129 + (i%128)] = w2[(oc*64 + i/128)*128 + (i%128)];
    for (int i=tid; i<128*PT; i+=256){
        int c=i/PT, px=i%PT;
        sx[i] = g_m1[((size_t)(b*128 + c))*Ll + p0+px];
    }
    __syncthreads();
    int og = tid % 16, pg = tid / 16;    // 16 o-groups x 16 px-groups
    int o0 = og*4, px0 = pg*4;
    int cnt = PT - px0; if (cnt > 4) cnt = 4; if (cnt < 0) cnt = 0;
    float acc[4][4];
    #pragma unroll
    for (int k=0;k<4;k++)
        #pragma unroll
        for (int j=0;j<4;j++) acc[k][j]=0.f;
    if (cnt > 0){
        for (int c=0;c<128;c++){
            float v0=sw[(o0+0)*129+c], v1=sw[(o0+1)*129+c], v2=sw[(o0+2)*129+c], v3=sw[(o0+3)*129+c];
            #pragma unroll 4
            for (int j=0;j<4;j++){
                if (j<cnt){
                    float xx = sx[c*PT + px0 + j];
                    acc[0][j]+=v0*xx; acc[1][j]+=v1*xx; acc[2][j]+=v2*xx; acc[3][j]+=v3*xx;
                }
            }
        }
        #pragma unroll
        for (int k=0;k<4;k++)
            for (int j=0;j<cnt;j++){
                int o = oc*64 + o0 + k;
                size_t idx = ((size_t)(b*DIMc + o))*Ll + p0+px0+j;
                out[idx] = x[idx] + bnf(acc[k][j], bn1, o, 256);
            }
    }
}

// ---------------- launch ----------------
extern "C" void kernel_launch(void* const* d_in, const int* in_sizes, int n_in,
                              void* d_out, int out_size){
    const float* x       = (const float*)d_in[0];
    const float* dw1_w   = (const float*)d_in[1];
    const float* dw1_b   = (const float*)d_in[2];
    const float* bn_dw1  = (const float*)d_in[3];
    const float* f1_w    = (const float*)d_in[4];
    const float* f1_b    = (const float*)d_in[5];
    const float* f2_w    = (const float*)d_in[6];
    const float* f2_b    = (const float*)d_in[7];
    const float* g_w     = (const float*)d_in[8];
    const float* g_b     = (const float*)d_in[9];
    const float* bn_g    = (const float*)d_in[10];
    const float* dw2_w   = (const float*)d_in[11];
    const float* dw2_b   = (const float*)d_in[12];
    const float* hatt1_w = (const float*)d_in[13];
    const float* vatt1_w = (const float*)d_in[14];
    const float* hatt2_w = (const float*)d_in[15];
    const float* vatt2_w = (const float*)d_in[16];
    const float* bn_mra  = (const float*)d_in[17];
    const float* bcdt_w  = (const float*)d_in[18];
    const float* ssd_dw_w= (const float*)d_in[19];
    const float* hz_w    = (const float*)d_in[20];
    const float* out_w   = (const float*)d_in[21];
    const float* A_param = (const float*)d_in[22];
    const float* D_param = (const float*)d_in[23];
    const float* qkv_w   = (const float*)d_in[24];
    const float* proj_w  = (const float*)d_in[25];
    const float* bn_n4   = (const float*)d_in[26];
    const float* mlp1_w  = (const float*)d_in[27];
    const float* bn_mlp  = (const float*)d_in[28];
    const float* mlp2_w  = (const float*)d_in[29];
    const float* bn_n1   = (const float*)d_in[30];
    float* out = (float*)d_out;
    (void)n_in; (void)in_sizes; (void)out_size;

    const int SM_A  = (192*65 + 64*PT) * 4;
    const int SM_B  = (3136 + 6272 + 8192) * 4;
    const int SM_C  = (6336 + 3168 + 2112 + 8320 + 4224) * 4;   // 96,640
    const int SM_X3 = (7232 + 4160) * 4;
    const int SM_M1 = (8224 + 12544) * 4;
    const int SM_M2 = (8256 + 6272) * 4;

    cudaFuncSetAttribute(k_stageA, cudaFuncAttributeMaxDynamicSharedMemorySize, SM_A);
    cudaFuncSetAttribute(k_stageB, cudaFuncAttributeMaxDynamicSharedMemorySize, SM_B);
    cudaFuncSetAttribute(k_stageC, cudaFuncAttributeMaxDynamicSharedMemorySize, SM_C);
    cudaFuncSetAttribute(k_x3,     cudaFuncAttributeMaxDynamicSharedMemorySize, SM_X3);
    cudaFuncSetAttribute(k_m1,     cudaFuncAttributeMaxDynamicSharedMemorySize, SM_M1);
    cudaFuncSetAttribute(k_m2,     cudaFuncAttributeMaxDynamicSharedMemorySize, SM_M2);

    k_stageA<<<2336, 256, SM_A>>>(x, dw1_w, dw1_b, bn_dw1,
                                  hatt1_w, vatt1_w, hatt2_w, vatt2_w, bn_mra,
                                  bcdt_w, qkv_w);
    k_stageB<<<768, 800, SM_B>>>(f1_w, f1_b, f2_w, f2_b, g_w, g_b, bn_g,
                                 ssd_dw_w, A_param);
    k_stageC<<<928, 512, SM_C>>>(x, dw2_w, dw2_b, hz_w, out_w, D_param,
                                 proj_w, bn_n4);
    k_x3<<<56, 512, SM_X3>>>(ssd_dw_w);
    k_m1<<<512, 256, SM_M1>>>(mlp1_w, bn_mlp);
    k_m2<<<512, 256, SM_M2>>>(x, mlp2_w, bn_n1, out);
}

// round 13
// speedup vs baseline: 1.3372x; 1.0029x over previous
#include <cuda_runtime.h>
#include <math.h>

#define Bq 8
#define Cc 64
#define Ll 784
#define HIDd 128
#define Sdim 64
#define NHh 16
#define DIMc 256
#define PT 49
#define NTt 16

// ---------------- scratch ----------------
__device__ float g_x1o [Bq*Cc*Ll];
__device__ float g_x1g [Bq*Cc*Ll];
__device__ float g_b1  [Bq*Cc*Ll];
__device__ float g_b2  [Bq*Cc*Ll];
__device__ float g_bcdt1[Bq*192*Ll];
__device__ float g_wsl [Bq*Sdim*Ll];
__device__ float g_h2  [Bq*Cc*Sdim];
__device__ float g_b3  [Bq*Cc*Ll];
__device__ float g_qb  [Bq*NHh*Ll*4];
__device__ float g_kb  [Bq*NHh*Ll*4];
__device__ float g_vb  [Bq*NHh*Ll*4];
__device__ float g_ob  [Bq*Ll*Cc];
__device__ float g_b4  [Bq*Cc*Ll];
__device__ float g_m1  [Bq*HIDd*Ll];

__device__ __forceinline__ float bnf(float x, const float* __restrict__ p, int c, int C){
    return (x - p[2*C+c]) * p[c] * rsqrtf(p[3*C+c] + 1e-5f) + p[C+c];
}

__device__ __forceinline__ unsigned long long pk2(float a, float b){
    unsigned long long r; asm("mov.b64 %0, {%1,%2};" : "=l"(r) : "f"(a), "f"(b)); return r;
}
__device__ __forceinline__ void upk2(unsigned long long v, float& a, float& b){
    asm("mov.b64 {%0,%1}, %2;" : "=f"(a), "=f"(b) : "l"(v));
}
__device__ __forceinline__ unsigned long long fma2(unsigned long long a, unsigned long long b, unsigned long long c){
    unsigned long long r; asm("fma.rn.f32x2 %0, %1, %2, %3;" : "=l"(r) : "l"(a), "l"(b), "l"(c)); return r;
}
__device__ __forceinline__ unsigned long long mul2(unsigned long long a, unsigned long long b){
    unsigned long long r; asm("mul.rn.f32x2 %0, %1, %2;" : "=l"(r) : "l"(a), "l"(b)); return r;
}

// =======================================================================
// STAGE A (256 thr): dw7a | att2 | bcdt | qkv   (unchanged)
// =======================================================================
__global__ void __launch_bounds__(256,1)
k_stageA(const float* __restrict__ x,
         const float* __restrict__ dw1_w, const float* __restrict__ dw1_b,
         const float* __restrict__ bn_dw1,
         const float* __restrict__ wh1, const float* __restrict__ wv1,
         const float* __restrict__ wh2, const float* __restrict__ wv2,
         const float* __restrict__ bnm,
         const float* __restrict__ bcdt_w, const float* __restrict__ qkv_w){
    extern __shared__ float pool[];
    int tid = threadIdx.x;
    int bid = blockIdx.x;

    if (bid < 1568){
        int idx = bid*256 + tid;
        int p = idx % Ll; int c = (idx/Ll) % Cc; int b = idx/(Ll*Cc);
        int y = p/28, xx = p%28;
        const float* ip = x + ((size_t)(b*DIMc + c))*Ll;
        const float* wc = dw1_w + c*49;
        float acc = dw1_b[c];
        #pragma unroll
        for (int ky=0; ky<7; ky++){
            int yy = y+ky-3; if ((unsigned)yy >= 28u) continue;
            #pragma unroll
            for (int kx=0; kx<7; kx++){
                int xw = xx+kx-3; if ((unsigned)xw >= 28u) continue;
                acc += wc[ky*7+kx] * ip[yy*28+xw];
            }
        }
        g_x1o[idx] = bnf(acc, bn_dw1, c, Cc);
        return;
    }
    if (bid < 2080){
        float* mp   = pool;
        float* xt   = pool + 784;
        float* sacc = pool + 884;
        float* sh   = pool + 984;
        float* cbuf = pool + 1174;
        float* sw1  = pool + 1364;
        float* sw2  = pool + 1397;
        float* sw3  = pool + 1430;
        float* sw4  = pool + 1463;
        int bc = bid - 1568; int b = bc/64, c = bc%64;
        if (tid < 33){ sw1[tid]=wh1[c*33+tid]; sw2[tid]=wv1[c*33+tid];
                       sw3[tid]=wh2[c*33+tid]; sw4[tid]=wv2[c*33+tid]; }
        const float* x2 = x + ((size_t)(b*DIMc + 64 + c))*Ll;
        for (int p=tid; p<784; p+=256){
            int y=p/28, xx=p%28;
            float m = -1e30f;
            #pragma unroll
            for (int dy=-1; dy<=1; dy++){ int yy=y+dy; if ((unsigned)yy>=28u) continue;
                #pragma unroll
                for (int dx=-1; dx<=1; dx++){ int xw=xx+dx; if ((unsigned)xw>=28u) continue;
                    m = fmaxf(m, x2[yy*28+xw]); } }
            mp[p] = m;
        }
        __syncthreads();
        if (tid < 100){
            int oy = tid/10, ox = tid%10;
            const float fa[4] = {1.f,3.f,3.f,1.f};
            float acc = 0.f;
            #pragma unroll
            for (int ty=0; ty<4; ty++){
                int q = 3*oy + ty - 1; if (q < 0) q = -q; if (q >= 28) q = 54 - q;
                #pragma unroll
                for (int tx=0; tx<4; tx++){
                    int r = 3*ox + tx - 1; if (r < 0) r = -r; if (r >= 28) r = 54 - r;
                    acc += fa[ty]*fa[tx]*mp[q*28+r];
                }
            }
            xt[tid] = acc * (1.0f/64.0f);
        }
        __syncthreads();
        if (tid < 100){
            int y = tid/10, xo = tid%10;
            float s = 0.f;
            #pragma unroll
            for (int ky=0; ky<11; ky++){ int yy=y+ky-5; if ((unsigned)yy>=10u) continue;
                #pragma unroll
                for (int kx=0; kx<3; kx++){ int xx=xo+kx-1; if ((unsigned)xx>=10u) continue;
                    s += sw1[ky*3+kx]*xt[yy*10+xx]; } }
            #pragma unroll
            for (int ky=0; ky<3; ky++){ int yy=y+ky-1; if ((unsigned)yy>=10u) continue;
                #pragma unroll
                for (int kx=0; kx<11; kx++){ int xx=xo+kx-5; if ((unsigned)xx>=10u) continue;
                    s += sw2[ky*11+kx]*xt[yy*10+xx]; } }
            sacc[tid] = s;
        }
        if (tid < 190){
            int r = tid/19, j = tid%19, d = j - r;
            sh[tid] = (d >= 0 && d < 10) ? xt[r*10 + d] : 0.f;
        }
        __syncthreads();
        if (tid < 190){
            int u = tid/19, v = tid%19;
            float s = 0.f;
            #pragma unroll
            for (int ky=0; ky<11; ky++){ int uu=u+ky-5; if ((unsigned)uu>=10u) continue;
                #pragma unroll
                for (int kx=0; kx<3; kx++){ int vv=v+kx-1; if ((unsigned)vv>=19u) continue;
                    s += sw3[ky*3+kx]*sh[uu*19+vv]; } }
            cbuf[tid] = s;
        }
        __syncthreads();
        if (tid < 100){
            int y = tid/10, xo = tid%10;
            sacc[tid] += cbuf[20*y + xo];
        }
        __syncthreads();
        if (tid < 190){
            int a = tid/10, b2 = tid%10, d = a - b2;
            sh[tid] = (d >= 0 && d < 10) ? xt[d*10 + b2] : 0.f;
        }
        __syncthreads();
        if (tid < 190){
            int a = tid/10, b2 = tid%10;
            float s = 0.f;
            #pragma unroll
            for (int ky=0; ky<3; ky++){ int av=a+ky-1; if ((unsigned)av>=19u) continue;
                #pragma unroll
                for (int kx=0; kx<11; kx++){ int bv=b2+kx-5; if ((unsigned)bv>=10u) continue;
                    s += sw4[ky*11+kx]*sh[av*10+bv]; } }
            cbuf[tid] = s;
        }
        __syncthreads();
        if (tid < 100){
            int y = tid/10, xo = tid%10;
            int g = 20*xo + y;
            float s = sacc[tid] + cbuf[(g%19)*10 + (g/19)];
            s = bnf(s, bnm, c, 64);
            sacc[tid] = 1.f/(1.f + __expf(-s));
        }
        __syncthreads();
        float* op = g_b2 + (size_t)bc*Ll;
        for (int p=tid; p<Ll; p+=256){
            int y = p/28, xx = p%28;
            op[p] = x2[p] * sacc[(y*10/28)*10 + (xx*10/28)];
        }
        return;
    }
    {
        int isQ = (bid >= 2208);
        int bidL = bid - (isQ ? 2208 : 2080);
        const float* w = isQ ? qkv_w : bcdt_w;
        int chOff = isQ ? 192 : 128;
        float* sw = pool;
        float* sx = pool + 192*65;
        int b = bidL / NTt, p0 = (bidL % NTt) * PT;
        for (int i=tid; i<192*64; i+=256){ sw[(i/64)*65 + (i%64)] = w[i]; }
        for (int i=tid; i<64*PT; i+=256){
            int c=i/PT, px=i%PT;
            sx[i] = x[((size_t)(b*DIMc + chOff + c))*Ll + p0+px];
        }
        __syncthreads();
        int og = tid % 48, pg = tid / 48;
        int o0 = og*4, px0 = pg*10;
        int cnt = PT - px0; if (cnt > 10) cnt = 10; if (cnt < 0) cnt = 0;
        float acc[4][10];
        #pragma unroll
        for (int k=0;k<4;k++)
            #pragma unroll
            for (int j=0;j<10;j++) acc[k][j]=0.f;
        if (cnt > 0){
            for (int c=0;c<64;c++){
                float w0=sw[(o0+0)*65+c], w1=sw[(o0+1)*65+c], w2=sw[(o0+2)*65+c], w3=sw[(o0+3)*65+c];
                #pragma unroll 10
                for (int j=0;j<10;j++){
                    if (j<cnt){
                        float xx = sx[c*PT + px0 + j];
                        acc[0][j]+=w0*xx; acc[1][j]+=w1*xx; acc[2][j]+=w2*xx; acc[3][j]+=w3*xx;
                    }
                }
            }
            if (!isQ){
                #pragma unroll
                for (int k=0;k<4;k++)
                    for (int j=0;j<cnt;j++)
                        g_bcdt1[((size_t)(b*192 + o0+k))*Ll + p0+px0+j] = acc[k][j];
            } else {
                #pragma unroll
                for (int k=0;k<4;k++){
                    int o = o0+k;
                    int part = o/64, rem = o%64, hh = rem/4, dd = rem%4;
                    float* dst = (part==0) ? g_qb : (part==1) ? g_kb : g_vb;
                    for (int j=0;j<cnt;j++)
                        dst[(((size_t)b*16 + hh)*Ll + p0+px0+j)*4 + dd] = acc[k][j];
                }
            }
        }
    }
}

// =======================================================================
// STAGE B (800 thr): star (f1+f2 fused pass) | softAB | attn
// =======================================================================
__global__ void __launch_bounds__(800,1)
k_stageB(const float* __restrict__ f1w, const float* __restrict__ f1b,
         const float* __restrict__ f2w, const float* __restrict__ f2b,
         const float* __restrict__ gw,  const float* __restrict__ gb,
         const float* __restrict__ bng,
         const float* __restrict__ ssd_dw, const float* __restrict__ Ap){
    extern __shared__ float pool[];
    int tid = threadIdx.x;
    int bid = blockIdx.x;

    if (bid < 128){
        float* sxv = pool;            // 3136
        float* sa  = pool + 3136;     // 6272
        float* wb1 = pool + 9408;     // 8192
        float* wb2 = pool + 17600;    // 8192
        int b = bid/16, p0 = (bid%16)*PT;
        for (int i=tid; i<64*PT; i+=800){
            int c=i/PT, px=i%PT;
            sxv[i] = g_x1o[((size_t)(b*64+c))*Ll + p0+px];
        }
        for (int i=tid; i<8192; i+=800){ wb1[i] = f1w[i]; wb2[i] = f2w[i]; }
        __syncthreads();
        for (int i=tid; i<128*PT; i+=800){
            int h=i/PT, px=i%PT;
            float a = f1b[h], a2 = f2b[h];
            const float* w1 = wb1 + h*64;
            const float* w2 = wb2 + h*64;
            #pragma unroll 8
            for (int c=0;c<64;c++){ float xc = sxv[c*PT+px]; a += w1[c]*xc; a2 += w2[c]*xc; }
            a = fminf(fmaxf(a,0.f),6.f);
            sa[i] = a*a2;
        }
        __syncthreads();
        for (int i=tid; i<8192; i+=800) wb1[i] = gw[i];
        __syncthreads();
        for (int i=tid; i<64*PT; i+=800){
            int o=i/PT, px=i%PT;
            float acc = gb[o];
            const float* wr = wb1 + o*128;
            #pragma unroll 8
            for (int j=0;j<128;j++) acc += wr[j]*sa[j*PT+px];
            g_x1g[((size_t)(b*64+o))*Ll + p0+px] = bnf(acc, bng, o, 64);
        }
        return;
    }
    if (bid < 640){
        float* rb  = pool;
        float* rd  = pool + 784;
        float* red = pool + 1568;
        int bs = bid - 128; int b = bs/64, s = bs%64;
        for (int i=tid; i<784; i+=800){
            rb[i] = g_bcdt1[((size_t)(b*192 + s))*Ll + i];
            rd[i] = g_bcdt1[((size_t)(b*192 + 128 + s))*Ll + i];
        }
        __syncthreads();
        float dtv = -1e30f, bmv = 0.f;
        if (tid < 784){
            int y = tid/28, xx = tid%28;
            const float* wB = ssd_dw + s*9;
            const float* wD = ssd_dw + (128+s)*9;
            float ab = 0.f, ad = 0.f;
            #pragma unroll
            for (int ky=0; ky<3; ky++){
                int yy=y+ky-1; if ((unsigned)yy>=28u) continue;
                #pragma unroll
                for (int kx=0; kx<3; kx++){
                    int xw=xx+kx-1; if ((unsigned)xw>=28u) continue;
                    float vB = rb[yy*28+xw], vD = rd[yy*28+xw];
                    ab += wB[ky*3+kx]*vB;
                    ad += wD[ky*3+kx]*vD;
                }
            }
            bmv = ab;
            dtv = ad + Ap[s];
        }
        float m = dtv;
        #pragma unroll
        for (int o=16;o;o>>=1) m = fmaxf(m, __shfl_xor_sync(0xFFFFFFFFu, m, o));
        if ((tid&31)==0) red[tid>>5] = m;
        __syncthreads();
        if (tid < 32){
            float v = (tid<25)? red[tid] : -1e30f;
            #pragma unroll
            for (int o=16;o;o>>=1) v = fmaxf(v, __shfl_xor_sync(0xFFFFFFFFu, v, o));
            if (tid==0) red[0]=v;
        }
        __syncthreads();
        m = red[0];
        __syncthreads();
        float e = (tid<784) ? __expf(dtv - m) : 0.f;
        float sum = e;
        #pragma unroll
        for (int o=16;o;o>>=1) sum += __shfl_xor_sync(0xFFFFFFFFu, sum, o);
        if ((tid&31)==0) red[tid>>5] = sum;
        __syncthreads();
        if (tid < 32){
            float v = (tid<25)? red[tid] : 0.f;
            #pragma unroll
            for (int o=16;o;o>>=1) v += __shfl_xor_sync(0xFFFFFFFFu, v, o);
            if (tid==0) red[0]=v;
        }
        __syncthreads();
        float inv = 1.f/red[0];
        if (tid < 784)
            g_wsl[((size_t)(b*64 + s))*Ll + tid] = e * inv * bmv;
        return;
    }
    {
        ulonglong2* KV = (ulonglong2*)pool;
        ulonglong2* VV = KV + Ll;
        int bh = bid - 640;
        size_t base4 = (size_t)bh * Ll;
        if (tid < 784){
            KV[tid] = ((const ulonglong2*)g_kb)[base4 + tid];
            VV[tid] = ((const ulonglong2*)g_vb)[base4 + tid];
        }
        __syncthreads();
        if (tid < 784){
            float4 q = ((const float4*)g_qb)[base4 + tid];
            const float CS = 0.7213475204444817f;
            unsigned long long q01 = pk2(q.x*CS, q.y*CS);
            unsigned long long q23 = pk2(q.z*CS, q.w*CS);
            unsigned long long a01 = pk2(0.f,0.f), a23 = pk2(0.f,0.f);
            float den = 0.f;
            #pragma unroll 4
            for (int j=0; j<Ll; j++){
                ulonglong2 kk = KV[j];
                ulonglong2 vv = VV[j];
                unsigned long long pr = fma2(q23, kk.y, mul2(q01, kk.x));
                float lo, hi; upk2(pr, lo, hi);
                float s = lo + hi;
                float e; asm("ex2.approx.f32 %0, %1;" : "=f"(e) : "f"(s));
                unsigned long long ee = pk2(e, e);
                a01 = fma2(ee, vv.x, a01);
                a23 = fma2(ee, vv.y, a23);
                den += e;
            }
            float inv = __frcp_rn(den);
            float a0,a1,a2,a3;
            upk2(a01,a0,a1); upk2(a23,a2,a3);
            int b = bh/16, hh = bh%16;
            float4 r; r.x=a0*inv; r.y=a1*inv; r.z=a2*inv; r.w=a3*inv;
            ((float4*)g_ob)[(((size_t)b*Ll + tid)*64 + hh*4)/4] = r;
        }
    }
}

// =======================================================================
// STAGE C (512 thr): dw7b [0,784) | ssd h+hz [784,800) | proj [800,928)
// =======================================================================
__global__ void __launch_bounds__(512,1)
k_stageC(const float* __restrict__ x,
         const float* __restrict__ dw2_w, const float* __restrict__ dw2_b,
         const float* __restrict__ hzw, const float* __restrict__ outw,
         const float* __restrict__ Dp,
         const float* __restrict__ pw, const float* __restrict__ bn4){
    extern __shared__ float pool[];
    int tid = threadIdx.x;
    int bid = blockIdx.x;

    if (bid < 784){
        int idx = bid*512 + tid;
        int p = idx % Ll; int c = (idx/Ll) % Cc; int b = idx/(Ll*Cc);
        int y = p/28, xx = p%28;
        const float* ip = g_x1g + ((size_t)(b*Cc + c))*Ll;
        const float* wc = dw2_w + c*49;
        float acc = dw2_b[c];
        #pragma unroll
        for (int ky=0; ky<7; ky++){
            int yy = y+ky-3; if ((unsigned)yy >= 28u) continue;
            #pragma unroll
            for (int kx=0; kx<7; kx++){
                int xw = xx+kx-3; if ((unsigned)xw >= 28u) continue;
                acc += wc[ky*7+kx] * ip[yy*28+xw];
            }
        }
        g_b1[idx] = acc;
        return;
    }
    if (bid < 800){
        float* sxb = pool;
        float* swl = pool + 6336;
        float* shh = pool + 9504;
        float* wz  = pool + 11616;
        float* zz  = pool + 19936;
        int bb = bid - 784;
        int b = bb >> 1, sh = bb & 1;
        int c0 = (tid & 15)*4, s0 = tid >> 4;
        float hacc[4] = {0.f,0.f,0.f,0.f};
        for (int ch=0; ch<8; ch++){
            int l0 = ch*98;
            for (int i=tid; i<64*98; i+=512){
                int c=i/98, l=i%98;
                sxb[c*99+l] = x[((size_t)(b*DIMc + 128 + c))*Ll + l0 + l];
            }
            for (int i=tid; i<32*98; i+=512){
                int sr=i/98, l=i%98;
                swl[sr*99+l] = g_wsl[((size_t)(b*64 + sh*32 + sr))*Ll + l0 + l];
            }
            __syncthreads();
            #pragma unroll 2
            for (int l=0; l<98; l++){
                float w0 = swl[s0*99+l];
                #pragma unroll
                for (int k=0;k<4;k++) hacc[k] += sxb[(c0+k)*99+l]*w0;
            }
            __syncthreads();
        }
        #pragma unroll
        for (int k=0;k<4;k++) shh[(c0+k)*33 + s0] = hacc[k];
        for (int i=tid; i<128*64; i+=512) wz[(i/64)*65 + (i%64)] = hzw[i];
        __syncthreads();
        for (int i=tid; i<128*32; i+=512){
            int o=i/32, s=i%32;
            float acc = 0.f;
            const float* wr = wz + o*65;
            #pragma unroll 8
            for (int c=0;c<64;c++) acc += wr[c]*shh[c*33+s];
            zz[o*33+s] = acc;
        }
        __syncthreads();
        float Dv = Dp[0];
        for (int i=tid; i<64*32; i+=512){
            int c=i/32, s=i%32;
            float hv = zz[c*33+s], z = zz[(64+c)*33+s];
            sxb[c*33+s] = hv * (z/(1.f+__expf(-z))) + hv*Dv;
        }
        __syncthreads();
        for (int i=tid; i<64*64; i+=512) wz[(i/64)*65 + (i%64)] = outw[i];
        __syncthreads();
        for (int i=tid; i<64*32; i+=512){
            int o=i/32, s=i%32;
            float acc = 0.f;
            const float* wr = wz + o*65;
            #pragma unroll 8
            for (int c=0;c<64;c++) acc += wr[c]*sxb[c*33+s];
            g_h2[((size_t)(b*64 + o))*64 + sh*32 + s] = acc;
        }
        return;
    }
    {
        float* sw  = pool;
        float* sx  = pool + 64*65;
        float* sbn = pool + 64*65 + 64*PT;
        int bidL = bid - 800;
        int b = bidL / NTt, p0 = (bidL % NTt) * PT;
        for (int i=tid; i<64*64; i+=512){ sw[(i/64)*65 + (i%64)] = pw[i]; }
        for (int i=tid; i<256; i+=512) sbn[i] = bn4[i];
        for (int i=tid; i<64*PT; i+=512){
            int c=i%64, px=i/64;
            sx[c*PT+px] = g_ob[((size_t)b*Ll + p0+px)*64 + c];
        }
        __syncthreads();
        for (int i=tid; i<64*PT; i+=512){
            int o=i/PT, px=i%PT;
            float acc = 0.f;
            const float* wr = sw + o*65;
            #pragma unroll 8
            for (int j=0;j<64;j++) acc += wr[j]*sx[j*PT+px];
            float xv = x[((size_t)(b*DIMc + 192 + o))*Ll + p0+px];
            g_b4[((size_t)(b*64+o))*Ll + p0+px] = bnf(xv + acc, sbn, o, 64);
        }
    }
}

// =======================================================================
// X3 (256 thr, 112 blocks): Cm = dw3(bcdt1[64+s]); b3 = h2 @ Cm, 56-px chunks,
// 4c x 4px register blocking (8 LDS per 16 FMA)
// =======================================================================
__global__ void __launch_bounds__(256,1)
k_x3(const float* __restrict__ ssd_dw){
    extern __shared__ float pool[];
    float* cm  = pool;             // 64*57 = 3648
    float* h2s = pool + 3648;      // 64*65 = 4160
    int b = blockIdx.x / 14, rc = blockIdx.x % 14;
    int p0 = rc*56;
    int tid = threadIdx.x;
    for (int i=tid; i<64*64; i+=256)
        h2s[(i/64)*65 + (i%64)] = g_h2[((size_t)b*64)*64 + i];
    for (int i=tid; i<64*56; i+=256){
        int s=i/56, lo=i%56;
        int p = p0+lo; int y=p/28, xx=p%28;
        const float* ip = g_bcdt1 + ((size_t)(b*192 + 64 + s))*Ll;
        const float* wc = ssd_dw + (64+s)*9;
        float acc = 0.f;
        #pragma unroll
        for (int ky=0; ky<3; ky++){
            int yy=y+ky-1; if ((unsigned)yy>=28u) continue;
            #pragma unroll
            for (int kx=0; kx<3; kx++){
                int xw=xx+kx-1; if ((unsigned)xw>=28u) continue;
                acc += wc[ky*3+kx]*ip[yy*28+xw];
            }
        }
        cm[s*57+lo] = acc;
    }
    __syncthreads();
    int cg = tid & 15, pg = tid >> 4;      // 16 c-groups x 16 px-groups
    int c0 = cg*4, px0 = pg*4;
    if (px0 < 56){
        float acc[4][4];
        #pragma unroll
        for (int k=0;k<4;k++)
            #pragma unroll
            for (int j=0;j<4;j++) acc[k][j]=0.f;
        #pragma unroll 4
        for (int s=0; s<64; s++){
            float c0v = cm[s*57+px0], c1v = cm[s*57+px0+1], c2v = cm[s*57+px0+2], c3v = cm[s*57+px0+3];
            #pragma unroll
            for (int k=0;k<4;k++){
                float hv = h2s[(c0+k)*65 + s];
                acc[k][0] += hv*c0v; acc[k][1] += hv*c1v;
                acc[k][2] += hv*c2v; acc[k][3] += hv*c3v;
            }
        }
        #pragma unroll
        for (int k=0;k<4;k++)
            #pragma unroll
            for (int j=0;j<4;j++)
                g_b3[((size_t)(b*64 + c0+k))*Ll + p0+px0+j] = acc[k][j];
    }
}

// =======================================================================
// M1 (256 thr, 512 blocks): mlp1 o-chunk of 32   (unchanged)
// =======================================================================
__global__ void __launch_bounds__(256,1)
k_m1(const float* __restrict__ w1, const float* __restrict__ bn_m){
    extern __shared__ float pool[];
    float* sw = pool;
    float* sx = pool + 8224;
    int b = blockIdx.x >> 6;
    int tile = (blockIdx.x >> 2) & 15;
    int oc = blockIdx.x & 3;
    int p0 = tile*PT;
    int tid = threadIdx.x;
    for (int i=tid; i<32*256; i+=256)
        sw[(i/256)*257 + (i%256)] = w1[(oc*32 + i/256)*256 + (i%256)];
    for (int i=tid; i<256*PT; i+=256){
        int c=i/PT, px=i%PT;
        const float* src = (c<64) ? g_b1 : (c<128) ? g_b2 : (c<192) ? g_b3 : g_b4;
        sx[i] = src[((size_t)(b*64 + (c&63)))*Ll + p0+px];
    }
    __syncthreads();
    int og = tid % 8, pg = tid / 8;
    int o0 = og*4, px0 = pg*2;
    int cnt = PT - px0; if (cnt > 2) cnt = 2; if (cnt < 0) cnt = 0;
    float acc[4][2];
    #pragma unroll
    for (int k=0;k<4;k++){ acc[k][0]=0.f; acc[k][1]=0.f; }
    if (cnt > 0){
        for (int c=0;c<256;c++){
            float v0=sw[(o0+0)*257+c], v1=sw[(o0+1)*257+c], v2=sw[(o0+2)*257+c], v3=sw[(o0+3)*257+c];
            float x0 = sx[c*PT + px0];
            float x1 = (cnt>1) ? sx[c*PT + px0 + 1] : 0.f;
            acc[0][0]+=v0*x0; acc[1][0]+=v1*x0; acc[2][0]+=v2*x0; acc[3][0]+=v3*x0;
            acc[0][1]+=v0*x1; acc[1][1]+=v1*x1; acc[2][1]+=v2*x1; acc[3][1]+=v3*x1;
        }
        #pragma unroll
        for (int k=0;k<4;k++)
            for (int j=0;j<cnt;j++){
                int o = oc*32 + o0 + k;
                float v = bnf(acc[k][j], bn_m, o, 128);
                g_m1[((size_t)(b*128 + o))*Ll + p0+px0+j] = fmaxf(v, 0.f);
            }
    }
}

// =======================================================================
// M2 (256 thr, 512 blocks): mlp2 o-chunk of 64 + residual   (unchanged)
// =======================================================================
__global__ void __launch_bounds__(256,1)
k_m2(const float* __restrict__ x, const float* __restrict__ w2,
     const float* __restrict__ bn1, float* __restrict__ out){
    extern __shared__ float pool[];
    float* sw = pool;
    float* sx = pool + 8256;
    int b = blockIdx.x >> 6;
    int tile = (blockIdx.x >> 2) & 15;
    int oc = blockIdx.x & 3;
    int p0 = tile*PT;
    int tid = threadIdx.x;
    for (int i=tid; i<64*128; i+=256)
        sw[(i/128)*129 + (i%128)] = w2[(oc*64 + i/128)*128 + (i%128)];
    for (int i=tid; i<128*PT; i+=256){
        int c=i/PT, px=i%PT;
        sx[i] = g_m1[((size_t)(b*128 + c))*Ll + p0+px];
    }
    __syncthreads();
    int og = tid % 16, pg = tid / 16;
    int o0 = og*4, px0 = pg*4;
    int cnt = PT - px0; if (cnt > 4) cnt = 4; if (cnt < 0) cnt = 0;
    float acc[4][4];
    #pragma unroll
    for (int k=0;k<4;k++)
        #pragma unroll
        for (int j=0;j<4;j++) acc[k][j]=0.f;
    if (cnt > 0){
        for (int c=0;c<128;c++){
            float v0=sw[(o0+0)*129+c], v1=sw[(o0+1)*129+c], v2=sw[(o0+2)*129+c], v3=sw[(o0+3)*129+c];
            #pragma unroll 4
            for (int j=0;j<4;j++){
                if (j<cnt){
                    float xx = sx[c*PT + px0 + j];
                    acc[0][j]+=v0*xx; acc[1][j]+=v1*xx; acc[2][j]+=v2*xx; acc[3][j]+=v3*xx;
                }
            }
        }
        #pragma unroll
        for (int k=0;k<4;k++)
            for (int j=0;j<cnt;j++){
                int o = oc*64 + o0 + k;
                size_t idx = ((size_t)(b*DIMc + o))*Ll + p0+px0+j;
                out[idx] = x[idx] + bnf(acc[k][j], bn1, o, 256);
            }
    }
}

// ---------------- launch ----------------
extern "C" void kernel_launch(void* const* d_in, const int* in_sizes, int n_in,
                              void* d_out, int out_size){
    const float* x       = (const float*)d_in[0];
    const float* dw1_w   = (const float*)d_in[1];
    const float* dw1_b   = (const float*)d_in[2];
    const float* bn_dw1  = (const float*)d_in[3];
    const float* f1_w    = (const float*)d_in[4];
    const float* f1_b    = (const float*)d_in[5];
    const float* f2_w    = (const float*)d_in[6];
    const float* f2_b    = (const float*)d_in[7];
    const float* g_w     = (const float*)d_in[8];
    const float* g_b     = (const float*)d_in[9];
    const float* bn_g    = (const float*)d_in[10];
    const float* dw2_w   = (const float*)d_in[11];
    const float* dw2_b   = (const float*)d_in[12];
    const float* hatt1_w = (const float*)d_in[13];
    const float* vatt1_w = (const float*)d_in[14];
    const float* hatt2_w = (const float*)d_in[15];
    const float* vatt2_w = (const float*)d_in[16];
    const float* bn_mra  = (const float*)d_in[17];
    const float* bcdt_w  = (const float*)d_in[18];
    const float* ssd_dw_w= (const float*)d_in[19];
    const float* hz_w    = (const float*)d_in[20];
    const float* out_w   = (const float*)d_in[21];
    const float* A_param = (const float*)d_in[22];
    const float* D_param = (const float*)d_in[23];
    const float* qkv_w   = (const float*)d_in[24];
    const float* proj_w  = (const float*)d_in[25];
    const float* bn_n4   = (const float*)d_in[26];
    const float* mlp1_w  = (const float*)d_in[27];
    const float* bn_mlp  = (const float*)d_in[28];
    const float* mlp2_w  = (const float*)d_in[29];
    const float* bn_n1   = (const float*)d_in[30];
    float* out = (float*)d_out;
    (void)n_in; (void)in_sizes; (void)out_size;

    const int SM_A  = (192*65 + 64*PT) * 4;
    const int SM_B  = (3136 + 6272 + 8192 + 8192) * 4;          // 103,168
    const int SM_C  = (6336 + 3168 + 2112 + 8320 + 4224) * 4;   // 96,640
    const int SM_X3 = (3648 + 4160) * 4;                         // 31,232
    const int SM_M1 = (8224 + 12544) * 4;
    const int SM_M2 = (8256 + 6272) * 4;

    cudaFuncSetAttribute(k_stageA, cudaFuncAttributeMaxDynamicSharedMemorySize, SM_A);
    cudaFuncSetAttribute(k_stageB, cudaFuncAttributeMaxDynamicSharedMemorySize, SM_B);
    cudaFuncSetAttribute(k_stageC, cudaFuncAttributeMaxDynamicSharedMemorySize, SM_C);
    cudaFuncSetAttribute(k_x3,     cudaFuncAttributeMaxDynamicSharedMemorySize, SM_X3);
    cudaFuncSetAttribute(k_m1,     cudaFuncAttributeMaxDynamicSharedMemorySize, SM_M1);
    cudaFuncSetAttribute(k_m2,     cudaFuncAttributeMaxDynamicSharedMemorySize, SM_M2);

    k_stageA<<<2336, 256, SM_A>>>(x, dw1_w, dw1_b, bn_dw1,
                                  hatt1_w, vatt1_w, hatt2_w, vatt2_w, bn_mra,
                                  bcdt_w, qkv_w);
    k_stageB<<<768, 800, SM_B>>>(f1_w, f1_b, f2_w, f2_b, g_w, g_b, bn_g,
                                 ssd_dw_w, A_param);
    k_stageC<<<928, 512, SM_C>>>(x, dw2_w, dw2_b, hz_w, out_w, D_param,
                                 proj_w, bn_n4);
    k_x3<<<112, 256, SM_X3>>>(ssd_dw_w);
    k_m1<<<512, 256, SM_M1>>>(mlp1_w, bn_mlp);
    k_m2<<<512, 256, SM_M2>>>(x, mlp2_w, bn_n1, out);
}

// round 15
// speedup vs baseline: 1.3749x; 1.0283x over previous
#include <cuda_runtime.h>
#include <math.h>

#define Bq 8
#define Cc 64
#define Ll 784
#define HIDd 128
#define Sdim 64
#define NHh 16
#define DIMc 256
#define PT 49
#define NTt 16

// ---------------- scratch ----------------
__device__ float g_x1o [Bq*Cc*Ll];
__device__ float g_x1g [Bq*Cc*Ll];
__device__ float g_b1  [Bq*Cc*Ll];
__device__ float g_b2  [Bq*Cc*Ll];
__device__ float g_bcdt1[Bq*192*Ll];
__device__ float g_wsl [Bq*Sdim*Ll];
__device__ float g_h2  [Bq*Cc*Sdim];
__device__ float g_b3  [Bq*Cc*Ll];
__device__ float g_qb  [Bq*NHh*Ll*4];
__device__ float g_kb  [Bq*NHh*Ll*4];
__device__ float g_vb  [Bq*NHh*Ll*4];
__device__ float g_ob  [Bq*Ll*Cc];
__device__ float g_b4  [Bq*Cc*Ll];
__device__ float g_m1  [Bq*HIDd*Ll];

__device__ __forceinline__ float bnf(float x, const float* __restrict__ p, int c, int C){
    return (x - p[2*C+c]) * p[c] * rsqrtf(p[3*C+c] + 1e-5f) + p[C+c];
}

__device__ __forceinline__ unsigned long long pk2(float a, float b){
    unsigned long long r; asm("mov.b64 %0, {%1,%2};" : "=l"(r) : "f"(a), "f"(b)); return r;
}
__device__ __forceinline__ void upk2(unsigned long long v, float& a, float& b){
    asm("mov.b64 {%0,%1}, %2;" : "=f"(a), "=f"(b) : "l"(v));
}
__device__ __forceinline__ unsigned long long fma2(unsigned long long a, unsigned long long b, unsigned long long c){
    unsigned long long r; asm("fma.rn.f32x2 %0, %1, %2, %3;" : "=l"(r) : "l"(a), "l"(b), "l"(c)); return r;
}
__device__ __forceinline__ unsigned long long mul2(unsigned long long a, unsigned long long b){
    unsigned long long r; asm("mul.rn.f32x2 %0, %1, %2;" : "=l"(r) : "l"(a), "l"(b)); return r;
}

// ---------------- branch 1 ----------------
__global__ void k_dw7a(const float* __restrict__ x, const float* __restrict__ w,
                       const float* __restrict__ bias, const float* __restrict__ bnp){
    int idx = blockIdx.x*256 + threadIdx.x;
    if (idx >= Bq*Cc*Ll) return;
    int p = idx % Ll; int c = (idx/Ll) % Cc; int b = idx/(Ll*Cc);
    int y = p/28, xx = p%28;
    const float* ip = x + ((size_t)(b*DIMc + c))*Ll;
    const float* wc = w + c*49;
    float acc = bias[c];
    #pragma unroll
    for (int ky=0; ky<7; ky++){
        int yy = y+ky-3; if ((unsigned)yy >= 28u) continue;
        #pragma unroll
        for (int kx=0; kx<7; kx++){
            int xw = xx+kx-3; if ((unsigned)xw >= 28u) continue;
            acc += wc[ky*7+kx] * ip[yy*28+xw];
        }
    }
    g_x1o[idx] = bnf(acc, bnp, c, Cc);
}

__global__ void k_dw7b(const float* __restrict__ w, const float* __restrict__ bias){
    int idx = blockIdx.x*256 + threadIdx.x;
    if (idx >= Bq*Cc*Ll) return;
    int p = idx % Ll; int c = (idx/Ll) % Cc; int b = idx/(Ll*Cc);
    int y = p/28, xx = p%28;
    const float* ip = g_x1g + ((size_t)(b*Cc + c))*Ll;
    const float* wc = w + c*49;
    float acc = bias[c];
    #pragma unroll
    for (int ky=0; ky<7; ky++){
        int yy = y+ky-3; if ((unsigned)yy >= 28u) continue;
        #pragma unroll
        for (int kx=0; kx<7; kx++){
            int xw = xx+kx-3; if ((unsigned)xw >= 28u) continue;
            acc += wc[ky*7+kx] * ip[yy*28+xw];
        }
    }
    g_b1[idx] = acc;
}

// star MLP (f1+f2 fused pass), 800 thr, 128 blocks
__global__ void __launch_bounds__(800,1)
k_star(const float* __restrict__ f1w, const float* __restrict__ f1b,
       const float* __restrict__ f2w, const float* __restrict__ f2b,
       const float* __restrict__ gw,  const float* __restrict__ gb,
       const float* __restrict__ bng){
    extern __shared__ float pool[];
    float* sxv = pool;            // 3136
    float* sa  = pool + 3136;     // 6272
    float* wb1 = pool + 9408;     // 8192
    float* wb2 = pool + 17600;    // 8192
    int tid = threadIdx.x;
    int b = blockIdx.x/16, p0 = (blockIdx.x%16)*PT;
    for (int i=tid; i<64*PT; i+=800){
        int c=i/PT, px=i%PT;
        sxv[i] = g_x1o[((size_t)(b*64+c))*Ll + p0+px];
    }
    for (int i=tid; i<8192; i+=800){ wb1[i] = f1w[i]; wb2[i] = f2w[i]; }
    __syncthreads();
    for (int i=tid; i<128*PT; i+=800){
        int h=i/PT, px=i%PT;
        float a = f1b[h], a2 = f2b[h];
        const float* w1 = wb1 + h*64;
        const float* w2 = wb2 + h*64;
        #pragma unroll 8
        for (int c=0;c<64;c++){ float xc = sxv[c*PT+px]; a += w1[c]*xc; a2 += w2[c]*xc; }
        a = fminf(fmaxf(a,0.f),6.f);
        sa[i] = a*a2;
    }
    __syncthreads();
    for (int i=tid; i<8192; i+=800) wb1[i] = gw[i];
    __syncthreads();
    for (int i=tid; i<64*PT; i+=800){
        int o=i/PT, px=i%PT;
        float acc = gb[o];
        const float* wr = wb1 + o*128;
        #pragma unroll 8
        for (int j=0;j<128;j++) acc += wr[j]*sa[j*PT+px];
        g_x1g[((size_t)(b*64+o))*Ll + p0+px] = bnf(acc, bng, o, 64);
    }
}

// ---------------- branch 2 ----------------
__global__ void k_att2(const float* __restrict__ x,
                       const float* __restrict__ wh1, const float* __restrict__ wv1,
                       const float* __restrict__ wh2, const float* __restrict__ wv2,
                       const float* __restrict__ bnm){
    __shared__ float mp[784], xt[100], sacc[100], sh[190], cbuf[190];
    __shared__ float sw1[33], sw2[33], sw3[33], sw4[33];
    int bc = blockIdx.x; int b = bc/64, c = bc%64;
    int tid = threadIdx.x;
    if (tid < 33){ sw1[tid]=wh1[c*33+tid]; sw2[tid]=wv1[c*33+tid];
                   sw3[tid]=wh2[c*33+tid]; sw4[tid]=wv2[c*33+tid]; }
    const float* x2 = x + ((size_t)(b*DIMc + 64 + c))*Ll;
    for (int p=tid; p<784; p+=256){
        int y=p/28, xx=p%28;
        float m = -1e30f;
        #pragma unroll
        for (int dy=-1; dy<=1; dy++){ int yy=y+dy; if ((unsigned)yy>=28u) continue;
            #pragma unroll
            for (int dx=-1; dx<=1; dx++){ int xw=xx+dx; if ((unsigned)xw>=28u) continue;
                m = fmaxf(m, x2[yy*28+xw]); } }
        mp[p] = m;
    }
    __syncthreads();
    if (tid < 100){
        int oy = tid/10, ox = tid%10;
        const float fa[4] = {1.f,3.f,3.f,1.f};
        float acc = 0.f;
        #pragma unroll
        for (int ty=0; ty<4; ty++){
            int q = 3*oy + ty - 1; if (q < 0) q = -q; if (q >= 28) q = 54 - q;
            #pragma unroll
            for (int tx=0; tx<4; tx++){
                int r = 3*ox + tx - 1; if (r < 0) r = -r; if (r >= 28) r = 54 - r;
                acc += fa[ty]*fa[tx]*mp[q*28+r];
            }
        }
        xt[tid] = acc * (1.0f/64.0f);
    }
    __syncthreads();
    if (tid < 100){
        int y = tid/10, xo = tid%10;
        float s = 0.f;
        #pragma unroll
        for (int ky=0; ky<11; ky++){ int yy=y+ky-5; if ((unsigned)yy>=10u) continue;
            #pragma unroll
            for (int kx=0; kx<3; kx++){ int xx=xo+kx-1; if ((unsigned)xx>=10u) continue;
                s += sw1[ky*3+kx]*xt[yy*10+xx]; } }
        #pragma unroll
        for (int ky=0; ky<3; ky++){ int yy=y+ky-1; if ((unsigned)yy>=10u) continue;
            #pragma unroll
            for (int kx=0; kx<11; kx++){ int xx=xo+kx-5; if ((unsigned)xx>=10u) continue;
                s += sw2[ky*11+kx]*xt[yy*10+xx]; } }
        sacc[tid] = s;
    }
    if (tid < 190){
        int r = tid/19, j = tid%19, d = j - r;
        sh[tid] = (d >= 0 && d < 10) ? xt[r*10 + d] : 0.f;
    }
    __syncthreads();
    if (tid < 190){
        int u = tid/19, v = tid%19;
        float s = 0.f;
        #pragma unroll
        for (int ky=0; ky<11; ky++){ int uu=u+ky-5; if ((unsigned)uu>=10u) continue;
            #pragma unroll
            for (int kx=0; kx<3; kx++){ int vv=v+kx-1; if ((unsigned)vv>=19u) continue;
                s += sw3[ky*3+kx]*sh[uu*19+vv]; } }
        cbuf[tid] = s;
    }
    __syncthreads();
    if (tid < 100){
        int y = tid/10, xo = tid%10;
        sacc[tid] += cbuf[20*y + xo];
    }
    __syncthreads();
    if (tid < 190){
        int a = tid/10, b2 = tid%10, d = a - b2;
        sh[tid] = (d >= 0 && d < 10) ? xt[d*10 + b2] : 0.f;
    }
    __syncthreads();
    if (tid < 190){
        int a = tid/10, b2 = tid%10;
        float s = 0.f;
        #pragma unroll
        for (int ky=0; ky<3; ky++){ int av=a+ky-1; if ((unsigned)av>=19u) continue;
            #pragma unroll
            for (int kx=0; kx<11; kx++){ int bv=b2+kx-5; if ((unsigned)bv>=10u) continue;
                s += sw4[ky*11+kx]*sh[av*10+bv]; } }
        cbuf[tid] = s;
    }
    __syncthreads();
    if (tid < 100){
        int y = tid/10, xo = tid%10;
        int g = 20*xo + y;
        float s = sacc[tid] + cbuf[(g%19)*10 + (g/19)];
        s = bnf(s, bnm, c, 64);
        sacc[tid] = 1.f/(1.f + __expf(-s));
    }
    __syncthreads();
    float* op = g_b2 + (size_t)bc*Ll;
    for (int p=tid; p<Ll; p+=256){
        int y = p/28, xx = p%28;
        op[p] = x2[p] * sacc[(y*10/28)*10 + (xx*10/28)];
    }
}

// ---------------- pw 192x64 (bcdt / qkv) ----------------
__global__ void __launch_bounds__(256,1)
k_pw192(const float* __restrict__ x, const float* __restrict__ w, int isQ){
    extern __shared__ float pool[];
    float* sw = pool;            // 192*65
    float* sx = pool + 192*65;   // 64*49
    int tid = threadIdx.x;
    int chOff = isQ ? 192 : 128;
    int b = blockIdx.x / NTt, p0 = (blockIdx.x % NTt) * PT;
    for (int i=tid; i<192*64; i+=256){ sw[(i/64)*65 + (i%64)] = w[i]; }
    for (int i=tid; i<64*PT; i+=256){
        int c=i/PT, px=i%PT;
        sx[i] = x[((size_t)(b*DIMc + chOff + c))*Ll + p0+px];
    }
    __syncthreads();
    int og = tid % 48, pg = tid / 48;
    int o0 = og*4, px0 = pg*10;
    int cnt = PT - px0; if (cnt > 10) cnt = 10; if (cnt < 0) cnt = 0;
    float acc[4][10];
    #pragma unroll
    for (int k=0;k<4;k++)
        #pragma unroll
        for (int j=0;j<10;j++) acc[k][j]=0.f;
    if (cnt > 0){
        for (int c=0;c<64;c++){
            float w0=sw[(o0+0)*65+c], w1=sw[(o0+1)*65+c], w2=sw[(o0+2)*65+c], w3=sw[(o0+3)*65+c];
            #pragma unroll 10
            for (int j=0;j<10;j++){
                if (j<cnt){
                    float xx = sx[c*PT + px0 + j];
                    acc[0][j]+=w0*xx; acc[1][j]+=w1*xx; acc[2][j]+=w2*xx; acc[3][j]+=w3*xx;
                }
            }
        }
        if (!isQ){
            #pragma unroll
            for (int k=0;k<4;k++)
                for (int j=0;j<cnt;j++)
                    g_bcdt1[((size_t)(b*192 + o0+k))*Ll + p0+px0+j] = acc[k][j];
        } else {
            #pragma unroll
            for (int k=0;k<4;k++){
                int o = o0+k;
                int part = o/64, rem = o%64, hh = rem/4, dd = rem%4;
                float* dst = (part==0) ? g_qb : (part==1) ? g_kb : g_vb;
                for (int j=0;j<cnt;j++)
                    dst[(((size_t)b*16 + hh)*Ll + p0+px0+j)*4 + dd] = acc[k][j];
            }
        }
    }
}

// ---------------- branch 3 ----------------
__global__ void __launch_bounds__(800,1)
k_softAB(const float* __restrict__ ssd_dw, const float* __restrict__ Ap){
    extern __shared__ float pool[];
    float* rb  = pool;          // 784
    float* rd  = pool + 784;    // 784
    float* red = pool + 1568;   // 32
    int tid = threadIdx.x;
    int bs = blockIdx.x; int b = bs/64, s = bs%64;
    for (int i=tid; i<784; i+=800){
        rb[i] = g_bcdt1[((size_t)(b*192 + s))*Ll + i];
        rd[i] = g_bcdt1[((size_t)(b*192 + 128 + s))*Ll + i];
    }
    __syncthreads();
    float dtv = -1e30f, bmv = 0.f;
    if (tid < 784){
        int y = tid/28, xx = tid%28;
        const float* wB = ssd_dw + s*9;
        const float* wD = ssd_dw + (128+s)*9;
        float ab = 0.f, ad = 0.f;
        #pragma unroll
        for (int ky=0; ky<3; ky++){
            int yy=y+ky-1; if ((unsigned)yy>=28u) continue;
            #pragma unroll
            for (int kx=0; kx<3; kx++){
                int xw=xx+kx-1; if ((unsigned)xw>=28u) continue;
                float vB = rb[yy*28+xw], vD = rd[yy*28+xw];
                ab += wB[ky*3+kx]*vB;
                ad += wD[ky*3+kx]*vD;
            }
        }
        bmv = ab;
        dtv = ad + Ap[s];
    }
    float m = dtv;
    #pragma unroll
    for (int o=16;o;o>>=1) m = fmaxf(m, __shfl_xor_sync(0xFFFFFFFFu, m, o));
    if ((tid&31)==0) red[tid>>5] = m;
    __syncthreads();
    if (tid < 32){
        float v = (tid<25)? red[tid] : -1e30f;
        #pragma unroll
        for (int o=16;o;o>>=1) v = fmaxf(v, __shfl_xor_sync(0xFFFFFFFFu, v, o));
        if (tid==0) red[0]=v;
    }
    __syncthreads();
    m = red[0];
    __syncthreads();
    float e = (tid<784) ? __expf(dtv - m) : 0.f;
    float sum = e;
    #pragma unroll
    for (int o=16;o;o>>=1) sum += __shfl_xor_sync(0xFFFFFFFFu, sum, o);
    if ((tid&31)==0) red[tid>>5] = sum;
    __syncthreads();
    if (tid < 32){
        float v = (tid<25)? red[tid] : 0.f;
        #pragma unroll
        for (int o=16;o;o>>=1) v += __shfl_xor_sync(0xFFFFFFFFu, v, o);
        if (tid==0) red[0]=v;
    }
    __syncthreads();
    float inv = 1.f/red[0];
    if (tid < 784)
        g_wsl[((size_t)(b*64 + s))*Ll + tid] = e * inv * bmv;
}

__global__ void __launch_bounds__(512,1)
k_ssdh(const float* __restrict__ x,
       const float* __restrict__ hzw, const float* __restrict__ outw,
       const float* __restrict__ Dp){
    extern __shared__ float pool[];
    float* sxb = pool;                 // 6336
    float* swl = pool + 6336;          // 3168
    float* shh = pool + 9504;          // 2112
    float* wz  = pool + 11616;         // 8320
    float* zz  = pool + 19936;         // 4224
    int tid = threadIdx.x;
    int bb = blockIdx.x;
    int b = bb >> 1, sh = bb & 1;
    int c0 = (tid & 15)*4, s0 = tid >> 4;
    float hacc[4] = {0.f,0.f,0.f,0.f};
    for (int ch=0; ch<8; ch++){
        int l0 = ch*98;
        for (int i=tid; i<64*98; i+=512){
            int c=i/98, l=i%98;
            sxb[c*99+l] = x[((size_t)(b*DIMc + 128 + c))*Ll + l0 + l];
        }
        for (int i=tid; i<32*98; i+=512){
            int sr=i/98, l=i%98;
            swl[sr*99+l] = g_wsl[((size_t)(b*64 + sh*32 + sr))*Ll + l0 + l];
        }
        __syncthreads();
        #pragma unroll 2
        for (int l=0; l<98; l++){
            float w0 = swl[s0*99+l];
            #pragma unroll
            for (int k=0;k<4;k++) hacc[k] += sxb[(c0+k)*99+l]*w0;
        }
        __syncthreads();
    }
    #pragma unroll
    for (int k=0;k<4;k++) shh[(c0+k)*33 + s0] = hacc[k];
    for (int i=tid; i<128*64; i+=512) wz[(i/64)*65 + (i%64)] = hzw[i];
    __syncthreads();
    for (int i=tid; i<128*32; i+=512){
        int o=i/32, s=i%32;
        float acc = 0.f;
        const float* wr = wz + o*65;
        #pragma unroll 8
        for (int c=0;c<64;c++) acc += wr[c]*shh[c*33+s];
        zz[o*33+s] = acc;
    }
    __syncthreads();
    float Dv = Dp[0];
    for (int i=tid; i<64*32; i+=512){
        int c=i/32, s=i%32;
        float hv = zz[c*33+s], z = zz[(64+c)*33+s];
        sxb[c*33+s] = hv * (z/(1.f+__expf(-z))) + hv*Dv;
    }
    __syncthreads();
    for (int i=tid; i<64*64; i+=512) wz[(i/64)*65 + (i%64)] = outw[i];
    __syncthreads();
    for (int i=tid; i<64*32; i+=512){
        int o=i/32, s=i%32;
        float acc = 0.f;
        const float* wr = wz + o*65;
        #pragma unroll 8
        for (int c=0;c<64;c++) acc += wr[c]*sxb[c*33+s];
        g_h2[((size_t)(b*64 + o))*64 + sh*32 + s] = acc;
    }
}

__global__ void __launch_bounds__(256,1)
k_x3(const float* __restrict__ ssd_dw){
    extern __shared__ float pool[];
    float* cm  = pool;             // 64*57 = 3648
    float* h2s = pool + 3648;      // 64*65 = 4160
    int b = blockIdx.x / 14, rc = blockIdx.x % 14;
    int p0 = rc*56;
    int tid = threadIdx.x;
    for (int i=tid; i<64*64; i+=256)
        h2s[(i/64)*65 + (i%64)] = g_h2[((size_t)b*64)*64 + i];
    for (int i=tid; i<64*56; i+=256){
        int s=i/56, lo=i%56;
        int p = p0+lo; int y=p/28, xx=p%28;
        const float* ip = g_bcdt1 + ((size_t)(b*192 + 64 + s))*Ll;
        const float* wc = ssd_dw + (64+s)*9;
        float acc = 0.f;
        #pragma unroll
        for (int ky=0; ky<3; ky++){
            int yy=y+ky-1; if ((unsigned)yy>=28u) continue;
            #pragma unroll
            for (int kx=0; kx<3; kx++){
                int xw=xx+kx-1; if ((unsigned)xw>=28u) continue;
                acc += wc[ky*3+kx]*ip[yy*28+xw];
            }
        }
        cm[s*57+lo] = acc;
    }
    __syncthreads();
    int cg = tid & 15, pg = tid >> 4;
    int c0 = cg*4, px0 = pg*4;
    if (px0 < 56){
        float acc[4][4];
        #pragma unroll
        for (int k=0;k<4;k++)
            #pragma unroll
            for (int j=0;j<4;j++) acc[k][j]=0.f;
        #pragma unroll 4
        for (int s=0; s<64; s++){
            float c0v = cm[s*57+px0], c1v = cm[s*57+px0+1], c2v = cm[s*57+px0+2], c3v = cm[s*57+px0+3];
            #pragma unroll
            for (int k=0;k<4;k++){
                float hv = h2s[(c0+k)*65 + s];
                acc[k][0] += hv*c0v; acc[k][1] += hv*c1v;
                acc[k][2] += hv*c2v; acc[k][3] += hv*c3v;
            }
        }
        #pragma unroll
        for (int k=0;k<4;k++)
            #pragma unroll
            for (int j=0;j<4;j++)
                g_b3[((size_t)(b*64 + c0+k))*Ll + p0+px0+j] = acc[k][j];
    }
}

// ---------------- branch 4 ----------------
__global__ void __launch_bounds__(784,1) k_attn(){
    __shared__ ulonglong2 KV[Ll];
    __shared__ ulonglong2 VV[Ll];
    int bh = blockIdx.x;
    size_t base4 = (size_t)bh * Ll;
    int tid = threadIdx.x;
    KV[tid] = ((const ulonglong2*)g_kb)[base4 + tid];
    VV[tid] = ((const ulonglong2*)g_vb)[base4 + tid];
    __syncthreads();
    float4 q = ((const float4*)g_qb)[base4 + tid];
    const float CS = 0.7213475204444817f;
    unsigned long long q01 = pk2(q.x*CS, q.y*CS);
    unsigned long long q23 = pk2(q.z*CS, q.w*CS);
    unsigned long long a01 = pk2(0.f,0.f), a23 = pk2(0.f,0.f);
    float den = 0.f;
    #pragma unroll 4
    for (int j=0; j<Ll; j++){
        ulonglong2 kk = KV[j];
        ulonglong2 vv = VV[j];
        unsigned long long pr = fma2(q23, kk.y, mul2(q01, kk.x));
        float lo, hi; upk2(pr, lo, hi);
        float s = lo + hi;
        float e; asm("ex2.approx.f32 %0, %1;" : "=f"(e) : "f"(s));
        unsigned long long ee = pk2(e, e);
        a01 = fma2(ee, vv.x, a01);
        a23 = fma2(ee, vv.y, a23);
        den += e;
    }
    float inv = __frcp_rn(den);
    float a0,a1,a2,a3;
    upk2(a01,a0,a1); upk2(a23,a2,a3);
    int b = bh/16, hh = bh%16;
    float4 r; r.x=a0*inv; r.y=a1*inv; r.z=a2*inv; r.w=a3*inv;
    ((float4*)g_ob)[(((size_t)b*Ll + tid)*64 + hh*4)/4] = r;
}

__global__ void __launch_bounds__(256,1)
k_proj(const float* __restrict__ x, const float* __restrict__ pw,
       const float* __restrict__ bnp){
    extern __shared__ float pool[];
    float* sw  = pool;
    float* sx  = pool + 64*65;
    float* sbn = pool + 64*65 + 64*PT;
    int tid = threadIdx.x;
    int b = blockIdx.x / NTt, p0 = (blockIdx.x % NTt) * PT;
    for (int i=tid; i<64*64; i+=256){ sw[(i/64)*65 + (i%64)] = pw[i]; }
    sbn[tid] = bnp[tid];
    for (int i=tid; i<64*PT; i+=256){
        int c=i%64, px=i/64;
        sx[c*PT+px] = g_ob[((size_t)b*Ll + p0+px)*64 + c];
    }
    __syncthreads();
    for (int i=tid; i<64*PT; i+=256){
        int o=i/PT, px=i%PT;
        float acc = 0.f;
        const float* wr = sw + o*65;
        #pragma unroll 8
        for (int j=0;j<64;j++) acc += wr[j]*sx[j*PT+px];
        float xv = x[((size_t)(b*DIMc + 192 + o))*Ll + p0+px];
        g_b4[((size_t)(b*64+o))*Ll + p0+px] = bnf(xv + acc, sbn, o, 64);
    }
}

// ---------------- merge MLP ----------------
__global__ void __launch_bounds__(256,1)
k_m1(const float* __restrict__ w1, const float* __restrict__ bn_m){
    extern __shared__ float pool[];
    float* sw = pool;
    float* sx = pool + 8224;
    int b = blockIdx.x >> 6;
    int tile = (blockIdx.x >> 2) & 15;
    int oc = blockIdx.x & 3;
    int p0 = tile*PT;
    int tid = threadIdx.x;
    for (int i=tid; i<32*256; i+=256)
        sw[(i/256)*257 + (i%256)] = w1[(oc*32 + i/256)*256 + (i%256)];
    for (int i=tid; i<256*PT; i+=256){
        int c=i/PT, px=i%PT;
        const float* src = (c<64) ? g_b1 : (c<128) ? g_b2 : (c<192) ? g_b3 : g_b4;
        sx[i] = src[((size_t)(b*64 + (c&63)))*Ll + p0+px];
    }
    __syncthreads();
    int og = tid % 8, pg = tid / 8;
    int o0 = og*4, px0 = pg*2;
    int cnt = PT - px0; if (cnt > 2) cnt = 2; if (cnt < 0) cnt = 0;
    float acc[4][2];
    #pragma unroll
    for (int k=0;k<4;k++){ acc[k][0]=0.f; acc[k][1]=0.f; }
    if (cnt > 0){
        for (int c=0;c<256;c++){
            float v0=sw[(o0+0)*257+c], v1=sw[(o0+1)*257+c], v2=sw[(o0+2)*257+c], v3=sw[(o0+3)*257+c];
            float x0 = sx[c*PT + px0];
            float x1 = (cnt>1) ? sx[c*PT + px0 + 1] : 0.f;
            acc[0][0]+=v0*x0; acc[1][0]+=v1*x0; acc[2][0]+=v2*x0; acc[3][0]+=v3*x0;
            acc[0][1]+=v0*x1; acc[1][1]+=v1*x1; acc[2][1]+=v2*x1; acc[3][1]+=v3*x1;
        }
        #pragma unroll
        for (int k=0;k<4;k++)
            for (int j=0;j<cnt;j++){
                int o = oc*32 + o0 + k;
                float v = bnf(acc[k][j], bn_m, o, 128);
                g_m1[((size_t)(b*128 + o))*Ll + p0+px0+j] = fmaxf(v, 0.f);
            }
    }
}

__global__ void __launch_bounds__(256,1)
k_m2(const float* __restrict__ x, const float* __restrict__ w2,
     const float* __restrict__ bn1, float* __restrict__ out){
    extern __shared__ float pool[];
    float* sw = pool;
    float* sx = pool + 8256;
    int b = blockIdx.x >> 6;
    int tile = (blockIdx.x >> 2) & 15;
    int oc = blockIdx.x & 3;
    int p0 = tile*PT;
    int tid = threadIdx.x;
    for (int i=tid; i<64*128; i+=256)
        sw[(i/128)*129 + (i%128)] = w2[(oc*64 + i/128)*128 + (i%128)];
    for (int i=tid; i<128*PT; i+=256){
        int c=i/PT, px=i%PT;
        sx[i] = g_m1[((size_t)(b*128 + c))*Ll + p0+px];
    }
    __syncthreads();
    int og = tid % 16, pg = tid / 16;
    int o0 = og*4, px0 = pg*4;
    int cnt = PT - px0; if (cnt > 4) cnt = 4; if (cnt < 0) cnt = 0;
    float acc[4][4];
    #pragma unroll
    for (int k=0;k<4;k++)
        #pragma unroll
        for (int j=0;j<4;j++) acc[k][j]=0.f;
    if (cnt > 0){
        for (int c=0;c<128;c++){
            float v0=sw[(o0+0)*129+c], v1=sw[(o0+1)*129+c], v2=sw[(o0+2)*129+c], v3=sw[(o0+3)*129+c];
            #pragma unroll 4
            for (int j=0;j<4;j++){
                if (j<cnt){
                    float xx = sx[c*PT + px0 + j];
                    acc[0][j]+=v0*xx; acc[1][j]+=v1*xx; acc[2][j]+=v2*xx; acc[3][j]+=v3*xx;
                }
            }
        }
        #pragma unroll
        for (int k=0;k<4;k++)
            for (int j=0;j<cnt;j++){
                int o = oc*64 + o0 + k;
                size_t idx = ((size_t)(b*DIMc + o))*Ll + p0+px0+j;
                out[idx] = x[idx] + bnf(acc[k][j], bn1, o, 256);
            }
    }
}

// ---------------- launch ----------------
extern "C" void kernel_launch(void* const* d_in, const int* in_sizes, int n_in,
                              void* d_out, int out_size){
    const float* x       = (const float*)d_in[0];
    const float* dw1_w   = (const float*)d_in[1];
    const float* dw1_b   = (const float*)d_in[2];
    const float* bn_dw1  = (const float*)d_in[3];
    const float* f1_w    = (const float*)d_in[4];
    const float* f1_b    = (const float*)d_in[5];
    const float* f2_w    = (const float*)d_in[6];
    const float* f2_b    = (const float*)d_in[7];
    const float* g_w     = (const float*)d_in[8];
    const float* g_b     = (const float*)d_in[9];
    const float* bn_g    = (const float*)d_in[10];
    const float* dw2_w   = (const float*)d_in[11];
    const float* dw2_b   = (const float*)d_in[12];
    const float* hatt1_w = (const float*)d_in[13];
    const float* vatt1_w = (const float*)d_in[14];
    const float* hatt2_w = (const float*)d_in[15];
    const float* vatt2_w = (const float*)d_in[16];
    const float* bn_mra  = (const float*)d_in[17];
    const float* bcdt_w  = (const float*)d_in[18];
    const float* ssd_dw_w= (const float*)d_in[19];
    const float* hz_w    = (const float*)d_in[20];
    const float* out_w   = (const float*)d_in[21];
    const float* A_param = (const float*)d_in[22];
    const float* D_param = (const float*)d_in[23];
    const float* qkv_w   = (const float*)d_in[24];
    const float* proj_w  = (const float*)d_in[25];
    const float* bn_n4   = (const float*)d_in[26];
    const float* mlp1_w  = (const float*)d_in[27];
    const float* bn_mlp  = (const float*)d_in[28];
    const float* mlp2_w  = (const float*)d_in[29];
    const float* bn_n1   = (const float*)d_in[30];
    float* out = (float*)d_out;
    (void)n_in; (void)in_sizes; (void)out_size;

    const int NE = Bq*Cc*Ll;

    const int SM_PW   = (192*65 + 64*PT) * 4;           // 62464
    const int SM_STAR = (3136 + 6272 + 8192 + 8192)*4;  // 103168
    const int SM_SOFT = 1600 * 4;                        // 6400
    const int SM_SSDH = (6336+3168+2112+8320+4224)*4;   // 96640
    const int SM_X3   = (3648 + 4160) * 4;               // 31232
    const int SM_PROJ = (64*65 + 64*PT + 256) * 4;       // 30208
    const int SM_M1   = (8224 + 12544) * 4;              // 83072
    const int SM_M2   = (8256 + 6272) * 4;               // 58112

    cudaFuncSetAttribute(k_pw192, cudaFuncAttributeMaxDynamicSharedMemorySize, SM_PW);
    cudaFuncSetAttribute(k_star,  cudaFuncAttributeMaxDynamicSharedMemorySize, SM_STAR);
    cudaFuncSetAttribute(k_softAB,cudaFuncAttributeMaxDynamicSharedMemorySize, SM_SOFT);
    cudaFuncSetAttribute(k_ssdh,  cudaFuncAttributeMaxDynamicSharedMemorySize, SM_SSDH);
    cudaFuncSetAttribute(k_x3,    cudaFuncAttributeMaxDynamicSharedMemorySize, SM_X3);
    cudaFuncSetAttribute(k_proj,  cudaFuncAttributeMaxDynamicSharedMemorySize, SM_PROJ);
    cudaFuncSetAttribute(k_m1,    cudaFuncAttributeMaxDynamicSharedMemorySize, SM_M1);
    cudaFuncSetAttribute(k_m2,    cudaFuncAttributeMaxDynamicSharedMemorySize, SM_M2);

    cudaStream_t s1, s2, s3;
    cudaStreamCreateWithFlags(&s1, cudaStreamNonBlocking);
    cudaStreamCreateWithFlags(&s2, cudaStreamNonBlocking);
    cudaStreamCreateWithFlags(&s3, cudaStreamNonBlocking);
    cudaEvent_t e0, e1, e2, e3;
    cudaEventCreateWithFlags(&e0, cudaEventDisableTiming);
    cudaEventCreateWithFlags(&e1, cudaEventDisableTiming);
    cudaEventCreateWithFlags(&e2, cudaEventDisableTiming);
    cudaEventCreateWithFlags(&e3, cudaEventDisableTiming);

    cudaEventRecord(e0, 0);
    cudaStreamWaitEvent(s1, e0, 0);
    cudaStreamWaitEvent(s2, e0, 0);
    cudaStreamWaitEvent(s3, e0, 0);

    // branch 1 on s1
    k_dw7a<<<(NE+255)/256, 256, 0, s1>>>(x, dw1_w, dw1_b, bn_dw1);
    k_star<<<128, 800, SM_STAR, s1>>>(f1_w, f1_b, f2_w, f2_b, g_w, g_b, bn_g);
    k_dw7b<<<(NE+255)/256, 256, 0, s1>>>(dw2_w, dw2_b);

    // branch 2 on s2
    k_att2<<<Bq*Cc, 256, 0, s2>>>(x, hatt1_w, vatt1_w, hatt2_w, vatt2_w, bn_mra);

    // branch 4 on s3
    k_pw192<<<128, 256, SM_PW, s3>>>(x, qkv_w, 1);
    k_attn<<<Bq*NHh, Ll, 0, s3>>>();
    k_proj<<<128, 256, SM_PROJ, s3>>>(x, proj_w, bn_n4);

    // branch 3 on legacy stream
    k_pw192<<<128, 256, SM_PW>>>(x, bcdt_w, 0);
    k_softAB<<<512, 800, SM_SOFT>>>(ssd_dw_w, A_param);
    k_ssdh<<<16, 512, SM_SSDH>>>(x, hz_w, out_w, D_param);
    k_x3<<<112, 256, SM_X3>>>(ssd_dw_w);

    // join
    cudaEventRecord(e1, s1); cudaStreamWaitEvent(0, e1, 0);
    cudaEventRecord(e2, s2); cudaStreamWaitEvent(0, e2, 0);
    cudaEventRecord(e3, s3); cudaStreamWaitEvent(0, e3, 0);

    // merge MLP
    k_m1<<<512, 256, SM_M1>>>(mlp1_w, bn_mlp);
    k_m2<<<512, 256, SM_M2>>>(x, mlp2_w, bn_n1, out);

    cudaEventDestroy(e0); cudaEventDestroy(e1);
    cudaEventDestroy(e2); cudaEventDestroy(e3);
    cudaStreamDestroy(s1); cudaStreamDestroy(s2); cudaStreamDestroy(s3);
}